// round 3
// baseline (speedup 1.0000x reference)
#include <cuda_runtime.h>

#define BATCH 256
#define TSTEPS 64

// ---------------- persistent state (device globals; no allocation) ----------
__device__ float g_v0[BATCH*20*24*24];
__device__ float g_i0[BATCH*20*24*24];
__device__ float g_v1[BATCH*50*8*8];
__device__ float g_i1[BATCH*50*8*8];
__device__ float g_v2[BATCH*500];
__device__ float g_i2[BATCH*500];
__device__ float g_vo[BATCH*10];
__device__ float g_io[BATCH*10];
__device__ float g_sp0[BATCH*20*12*12];   // layer-0 pooled spikes (0/1)
__device__ float g_sp1[BATCH*800];        // layer-1 pooled spikes, flattened
__device__ float g_sp2[BATCH*500];        // layer-2 spikes
__device__ float g_w2r[500*50];           // conv2 weights RAW, [ci*25+k][co]

#define LIF_BETA 0.1f
#define LIF_IDEC 0.8f
#define LIF_VTH  1.0f

// LIF update with STRICT per-op rounding (no FMA contraction), matching
// XLA's elementwise semantics:
//   v_dec = v + (beta * (i - v));  z = (v_dec - 1 > 0);
//   v'    = (1 - z) * v_dec;       i' = (0.8 * i) + inp
__device__ __forceinline__ void lif_update(float& v, float& i, float inp, float& z)
{
    float vd = __fadd_rn(v, __fmul_rn(LIF_BETA, __fsub_rn(i, v)));
    z = (vd > LIF_VTH) ? 1.f : 0.f;
    v = __fmul_rn(__fsub_rn(1.f, z), vd);
    i = __fadd_rn(__fmul_rn(LIF_IDEC, i), inp);
}

// ---------------- setup kernels ---------------------------------------------
__global__ void zero_states() {
    int i = blockIdx.x * blockDim.x + threadIdx.x;
    const int n0 = BATCH*20*24*24;
    if (i < n0)          { g_v0[i] = 0.f; g_i0[i] = 0.f; }
    if (i < BATCH*50*64) { g_v1[i] = 0.f; g_i1[i] = 0.f; }
    if (i < BATCH*500)   { g_v2[i] = 0.f; g_i2[i] = 0.f; }
    if (i < BATCH*10)    { g_vo[i] = 0.f; g_io[i] = 0.f; }
}

__global__ void reorder_w2(const float* __restrict__ w2) {
    int i = blockIdx.x * blockDim.x + threadIdx.x;   // over 50*20*25 = 25000
    if (i < 25000) {
        int co = i / 500;
        int r  = i % 500;     // r = ci*25 + k
        g_w2r[r*50 + co] = w2[i];
    }
}

// ---------------- K1: conv1 (1->20, 5x5) + LIF + 2x2 maxpool ----------------
__global__ __launch_bounds__(160) void k_conv1(
    const float* __restrict__ x, const float* __restrict__ w1,
    const float* __restrict__ b1, int t)
{
    __shared__ float sx[784];
    __shared__ float sw[25];
    int b = blockIdx.x, c = blockIdx.y;
    int tid = threadIdx.x;
    const float* xp = x + ((size_t)t * BATCH + b) * 784;
    for (int i = tid; i < 784; i += 160) sx[i] = xp[i];
    if (tid < 25) sw[tid] = w1[c*25 + tid];
    __syncthreads();
    if (tid >= 144) return;

    int yp = tid / 12, xq = tid % 12;
    int y0 = 2*yp, x0 = 2*xq;

    float in[6][6];
#pragma unroll
    for (int i = 0; i < 6; i++)
#pragma unroll
        for (int j = 0; j < 6; j++)
            in[i][j] = sx[(y0+i)*28 + x0 + j];

    double acc[2][2] = {{0.0,0.0},{0.0,0.0}};
#pragma unroll
    for (int ki = 0; ki < 5; ki++)
#pragma unroll
        for (int kj = 0; kj < 5; kj++) {
            double w = (double)sw[ki*5 + kj];
            acc[0][0] += (double)in[ki  ][kj  ] * w;
            acc[0][1] += (double)in[ki  ][kj+1] * w;
            acc[1][0] += (double)in[ki+1][kj  ] * w;
            acc[1][1] += (double)in[ki+1][kj+1] * w;
        }

    float bias = __ldg(&b1[c]);
    int base = ((b*20 + c)*24 + y0)*24 + x0;
    float zmax = 0.f;
#pragma unroll
    for (int dy = 0; dy < 2; dy++) {
        int idx = base + dy*24;
        float2 v  = *(float2*)&g_v0[idx];
        float2 ii = *(float2*)&g_i0[idx];
        float inp0 = __fadd_rn((float)acc[dy][0], bias);
        float inp1 = __fadd_rn((float)acc[dy][1], bias);
        float z0, z1;
        lif_update(v.x, ii.x, inp0, z0);
        lif_update(v.y, ii.y, inp1, z1);
        *(float2*)&g_v0[idx] = v;
        *(float2*)&g_i0[idx] = ii;
        zmax = fmaxf(zmax, fmaxf(z0, z1));
    }
    g_sp0[(b*20 + c)*144 + yp*12 + xq] = zmax;
}

// ---------------- K2: conv2 (20->50, 5x5, x10) + LIF + 2x2 maxpool ----------
__global__ __launch_bounds__(400) void k_conv2(const float* __restrict__ b2)
{
    __shared__ float s[2880];               // [20][12][12]
    int b = blockIdx.x, tid = threadIdx.x;
    for (int i = tid; i < 2880; i += 400) s[i] = g_sp0[b*2880 + i];
    __syncthreads();

    int pos = tid & 15, cp = tid >> 4;      // cp in [0,25)
    int yp = pos >> 2, xq = pos & 3;

    double acc[2][2][2];
#pragma unroll
    for (int c = 0; c < 2; c++)
#pragma unroll
        for (int dy = 0; dy < 2; dy++)
#pragma unroll
            for (int dx = 0; dx < 2; dx++) acc[c][dy][dx] = 0.0;

#pragma unroll 1
    for (int ci = 0; ci < 20; ci++) {
        float in[6][6];
#pragma unroll
        for (int i = 0; i < 6; i++)
#pragma unroll
            for (int j = 0; j < 6; j++)
                in[i][j] = s[ci*144 + (2*yp + i)*12 + 2*xq + j];
#pragma unroll
        for (int k = 0; k < 25; k++) {
            int ky = k / 5, kx = k % 5;
            const float* wr = &g_w2r[(ci*25 + k)*50];
            double w0  = (double)__ldg(wr + cp);
            double w1v = (double)__ldg(wr + cp + 25);
#pragma unroll
            for (int dy = 0; dy < 2; dy++)
#pragma unroll
                for (int dx = 0; dx < 2; dx++) {
                    double a = (double)in[ky+dy][kx+dx];
                    acc[0][dy][dx] += a * w0;
                    acc[1][dy][dx] += a * w1v;
                }
        }
    }

#pragma unroll
    for (int c = 0; c < 2; c++) {
        int co = cp + c*25;
        float bias = __ldg(&b2[co]);
        float zmax = 0.f;
#pragma unroll
        for (int dy = 0; dy < 2; dy++) {
            int y = 2*yp + dy;
            int idx = ((b*50 + co)*8 + y)*8 + 2*xq;
            float2 v  = *(float2*)&g_v1[idx];
            float2 ii = *(float2*)&g_i1[idx];
            // reference order: conv sum (exact), +b (rounded), *10 (rounded)
            float inp0 = __fmul_rn(10.0f, __fadd_rn((float)acc[c][dy][0], bias));
            float inp1 = __fmul_rn(10.0f, __fadd_rn((float)acc[c][dy][1], bias));
            float z0, z1;
            lif_update(v.x, ii.x, inp0, z0);
            lif_update(v.y, ii.y, inp1, z1);
            *(float2*)&g_v1[idx] = v;
            *(float2*)&g_i1[idx] = ii;
            zmax = fmaxf(zmax, fmaxf(z0, z1));
        }
        g_sp1[b*800 + co*16 + yp*4 + xq] = zmax;
    }
}

// ---------------- K3a: FC 800->500 + LIF2 -----------------------------------
__global__ __launch_bounds__(200) void k_fc(
    const float* __restrict__ w_fc, const float* __restrict__ b_fc)
{
    __shared__ __align__(16) float sA[32][52];   // [kk][m]
    __shared__ __align__(16) float sB[32][18];   // [kk][n]
    int mt = blockIdx.x;          // 0..9
    int nt = blockIdx.y;          // 0..15
    int tid = threadIdx.x;        // 0..199
    int m = 2 * (tid % 25);
    int n = 2 * (tid / 25);

    double acc[2][2] = {{0.0,0.0},{0.0,0.0}};
    for (int k0 = 0; k0 < 800; k0 += 32) {
        __syncthreads();
        for (int idx = tid; idx < 50*32; idx += 200) {
            int kk = idx & 31, mm = idx >> 5;
            sA[kk][mm] = w_fc[(mt*50 + mm)*800 + k0 + kk];
        }
        for (int idx = tid; idx < 16*32; idx += 200) {
            int kk = idx & 31, nn = idx >> 5;
            sB[kk][nn] = g_sp1[(nt*16 + nn)*800 + k0 + kk];
        }
        __syncthreads();
#pragma unroll
        for (int kk = 0; kk < 32; kk++) {
            float2 a = *(const float2*)&sA[kk][m];
            float2 bv = *(const float2*)&sB[kk][n];
            double ax = (double)a.x, ay = (double)a.y;
            double bx = (double)bv.x, by = (double)bv.y;
            acc[0][0] += ax * bx;
            acc[0][1] += ax * by;
            acc[1][0] += ay * bx;
            acc[1][1] += ay * by;
        }
    }

#pragma unroll
    for (int dm = 0; dm < 2; dm++)
#pragma unroll
        for (int dn = 0; dn < 2; dn++) {
            int mo = mt*50 + m + dm;
            int no = nt*16 + n + dn;
            float inp = __fadd_rn((float)acc[dm][dn], __ldg(&b_fc[mo]));
            int sidx = no*500 + mo;
            float v = g_v2[sidx], ii = g_i2[sidx];
            float z;
            lif_update(v, ii, inp, z);
            g_v2[sidx] = v;
            g_i2[sidx] = ii;
            g_sp2[sidx] = z;
        }
}

// ---------------- K3b: readout GEMM 500->10 + LI cell + voltage write -------
__global__ __launch_bounds__(320) void k_out(
    const float* __restrict__ w_out, float* __restrict__ volt, int t)
{
    __shared__ float sz[500];
    int b = blockIdx.x, tid = threadIdx.x;
    for (int i = tid; i < 500; i += 320) sz[i] = g_sp2[b*500 + i];
    __syncthreads();
    int w = tid >> 5, lane = tid & 31;
    double sum = 0.0;
    for (int j = lane; j < 500; j += 32)
        sum += (double)sz[j] * (double)__ldg(&w_out[w*500 + j]);
#pragma unroll
    for (int off = 16; off; off >>= 1)
        sum += __shfl_xor_sync(0xffffffffu, sum, off);
    if (lane == 0) {
        int idx = b*10 + w;
        float vo = g_vo[idx], io = g_io[idx];
        // LI: v' = vo + (0.1*(io - vo)); i' = (0.8*io) + sum   (no FMA)
        float vn = __fadd_rn(vo, __fmul_rn(LIF_BETA, __fsub_rn(io, vo)));
        g_vo[idx] = vn;
        g_io[idx] = __fadd_rn(__fmul_rn(LIF_IDEC, io), (float)sum);
        volt[((size_t)t * BATCH + b)*10 + w] = vn;
    }
}

// ---------------- launch -----------------------------------------------------
extern "C" void kernel_launch(void* const* d_in, const int* in_sizes, int n_in,
                              void* d_out, int out_size)
{
    const float* x     = (const float*)d_in[0];
    const float* w1    = (const float*)d_in[1];
    const float* b1    = (const float*)d_in[2];
    const float* w2    = (const float*)d_in[3];
    const float* b2    = (const float*)d_in[4];
    const float* w_fc  = (const float*)d_in[5];
    const float* b_fc  = (const float*)d_in[6];
    const float* w_out = (const float*)d_in[7];
    float* volt = (float*)d_out;

    zero_states<<<(BATCH*20*24*24 + 255)/256, 256>>>();
    reorder_w2<<<(25000 + 255)/256, 256>>>(w2);

    for (int t = 0; t < TSTEPS; t++) {
        dim3 g1(BATCH, 20);
        k_conv1<<<g1, 160>>>(x, w1, b1, t);
        k_conv2<<<BATCH, 400>>>(b2);
        dim3 g3(10, 16);
        k_fc<<<g3, 200>>>(w_fc, b_fc);
        k_out<<<BATCH, 320>>>(w_out, volt, t);
    }
}

// round 5
// speedup vs baseline: 5.9120x; 5.9120x over previous
#include <cuda_runtime.h>

#define BATCH 256
#define TSTEPS 64

#define SCALE_F  4503599627370496.0f      // 2^52
#define INV_SCALE 2.220446049250313e-16   // 2^-52 (double)

// ---------------- persistent state (device globals; no allocation) ----------
__device__ float g_v0[BATCH*20*24*24];
__device__ float g_i0[BATCH*20*24*24];
__device__ float g_v1[BATCH*64*64];       // [b][pos(8x8)][co padded to 64]
__device__ float g_i1[BATCH*64*64];
__device__ float g_v2[BATCH*512];         // [b][m padded to 512]
__device__ float g_i2[BATCH*512];
__device__ float g_vo[BATCH*10];
__device__ float g_io[BATCH*10];
__device__ float g_sp0[BATCH*20*12*12];   // layer-0 pooled spikes (0/1)
__device__ float g_sp1[BATCH*800];        // layer-1 pooled spikes (co*16+pos)
__device__ long long g_w2ll[512*64];      // conv2 w * 2^52, [t pad 512][co pad 64]
__device__ long long g_wfcll[800*512];    // fc w * 2^52, [k][m pad 512]
__device__ long long g_woutll[10*500];    // w_out * 2^52

#define LIF_BETA 0.1f
#define LIF_IDEC 0.8f
#define LIF_VTH  1.0f

// LIF update with STRICT per-op rounding (no FMA contraction):
__device__ __forceinline__ void lif_update(float& v, float& i, float inp, float& z)
{
    float vd = __fadd_rn(v, __fmul_rn(LIF_BETA, __fsub_rn(i, v)));
    z = (vd > LIF_VTH) ? 1.f : 0.f;
    v = __fmul_rn(__fsub_rn(1.f, z), vd);
    i = __fadd_rn(__fmul_rn(LIF_IDEC, i), inp);
}

__device__ __forceinline__ float fx2f(long long acc)
{
    return (float)((double)acc * INV_SCALE);
}

// ---------------- setup kernels ---------------------------------------------
__global__ void zero_states() {
    int i = blockIdx.x * blockDim.x + threadIdx.x;
    if (i < BATCH*20*24*24) { g_v0[i] = 0.f; g_i0[i] = 0.f; }
    if (i < BATCH*64*64)    { g_v1[i] = 0.f; g_i1[i] = 0.f; }
    if (i < BATCH*512)      { g_v2[i] = 0.f; g_i2[i] = 0.f; }
    if (i < BATCH*10)       { g_vo[i] = 0.f; g_io[i] = 0.f; }
}

__global__ void prep_weights(const float* __restrict__ w2,
                             const float* __restrict__ w_fc,
                             const float* __restrict__ w_out) {
    int i = blockIdx.x * blockDim.x + threadIdx.x;
    if (i < 512*64) {                 // conv2: [t][co], t = ci*25+k
        int t = i >> 6, co = i & 63;
        float w = (t < 500 && co < 50) ? w2[co*500 + t] : 0.f;
        g_w2ll[i] = __float2ll_rn(__fmul_rn(w, SCALE_F));   // exact (pow2 scale)
    }
    if (i < 800*512) {                // fc transpose: [k][m]
        int k = i >> 9, m = i & 511;
        float w = (m < 500) ? w_fc[m*800 + k] : 0.f;
        g_wfcll[i] = __float2ll_rn(__fmul_rn(w, SCALE_F));
    }
    if (i < 10*500) {
        g_woutll[i] = __float2ll_rn(__fmul_rn(w_out[i], SCALE_F));
    }
}

// ---------------- K1: conv1 (1->20, 5x5) + LIF + 2x2 maxpool ----------------
// grid (B, 20), block 160. Thread = one pooled output (12x12).
// Exact accumulation: TwoProdFMA (p,e) -> int64 fixed point @ 2^-52.
__global__ __launch_bounds__(160) void k_conv1(
    const float* __restrict__ x, const float* __restrict__ w1,
    const float* __restrict__ b1, int t)
{
    __shared__ float sx[784];
    __shared__ float sw[25];
    int b = blockIdx.x, cch = blockIdx.y;
    int tid = threadIdx.x;
    const float* xp = x + ((size_t)t * BATCH + b) * 784;
    for (int i = tid; i < 784; i += 160) sx[i] = xp[i];
    if (tid < 25) sw[tid] = w1[cch*25 + tid];
    __syncthreads();
    if (tid >= 144) return;

    int yp = tid / 12, xq = tid % 12;
    int y0 = 2*yp, x0 = 2*xq;

    float in[6][6];
#pragma unroll
    for (int i = 0; i < 6; i++)
#pragma unroll
        for (int j = 0; j < 6; j++)
            in[i][j] = sx[(y0+i)*28 + x0 + j];

    long long a00 = 0, a01 = 0, a10 = 0, a11 = 0;
#pragma unroll
    for (int ki = 0; ki < 5; ki++)
#pragma unroll
        for (int kj = 0; kj < 5; kj++) {
            float w = sw[ki*5 + kj];
            {   float a = in[ki  ][kj  ];
                float p = __fmul_rn(a, w);
                float e = __fmaf_rn(a, w, -p);
                a00 += __float2ll_rn(__fmul_rn(p, SCALE_F))
                     + __float2ll_rn(__fmul_rn(e, SCALE_F)); }
            {   float a = in[ki  ][kj+1];
                float p = __fmul_rn(a, w);
                float e = __fmaf_rn(a, w, -p);
                a01 += __float2ll_rn(__fmul_rn(p, SCALE_F))
                     + __float2ll_rn(__fmul_rn(e, SCALE_F)); }
            {   float a = in[ki+1][kj  ];
                float p = __fmul_rn(a, w);
                float e = __fmaf_rn(a, w, -p);
                a10 += __float2ll_rn(__fmul_rn(p, SCALE_F))
                     + __float2ll_rn(__fmul_rn(e, SCALE_F)); }
            {   float a = in[ki+1][kj+1];
                float p = __fmul_rn(a, w);
                float e = __fmaf_rn(a, w, -p);
                a11 += __float2ll_rn(__fmul_rn(p, SCALE_F))
                     + __float2ll_rn(__fmul_rn(e, SCALE_F)); }
        }
    float sum[2][2] = {{fx2f(a00), fx2f(a01)}, {fx2f(a10), fx2f(a11)}};

    float bias = __ldg(&b1[cch]);
    int base = ((b*20 + cch)*24 + y0)*24 + x0;
    float zmax = 0.f;
#pragma unroll
    for (int dy = 0; dy < 2; dy++) {
        int idx = base + dy*24;
        float2 v  = *(float2*)&g_v0[idx];
        float2 ii = *(float2*)&g_i0[idx];
        float inp0 = __fadd_rn(sum[dy][0], bias);
        float inp1 = __fadd_rn(sum[dy][1], bias);
        float z0, z1;
        lif_update(v.x, ii.x, inp0, z0);
        lif_update(v.y, ii.y, inp1, z1);
        *(float2*)&g_v0[idx] = v;
        *(float2*)&g_i0[idx] = ii;
        zmax = fmaxf(zmax, fmaxf(z0, z1));
    }
    g_sp0[(b*20 + cch)*144 + yp*12 + xq] = zmax;
}

// ---------------- K2: conv2 (20->50, 5x5, x10) + LIF + 2x2 maxpool ----------
// Block = one sample (512 thr, 16 warps). Warp = pooled pos; lane = co (+co+32).
// Sparse: ballot over 32-term chunks; selected terms add exact int64 weights.
__global__ __launch_bounds__(512) void k_conv2(const float* __restrict__ b2)
{
    __shared__ float s_in[2880];    // [20][12][12]
    __shared__ int   s_off[512];    // input offset per term
    int b = blockIdx.x, tid = threadIdx.x;
    for (int i = tid; i < 2880; i += 512) s_in[i] = g_sp0[b*2880 + i];
    {
        int tt = (tid < 500) ? tid : 0;
        int ci = tt / 25, k = tt % 25;
        s_off[tid] = ci*144 + (k/5)*12 + (k%5);
    }
    __syncthreads();

    int warp = tid >> 5, lane = tid & 31;
    int yp = warp >> 2, xq = warp & 3;
    int co = lane;
    int co2 = lane + 32;

    float bias0 = __ldg(&b2[co]);
    float bias1 = (co2 < 50) ? __ldg(&b2[co2]) : 0.f;

    float z0max = 0.f, z1max = 0.f;

#pragma unroll
    for (int sp = 0; sp < 4; sp++) {
        int dy = sp >> 1, dx = sp & 1;
        int y = 2*yp + dy, x = 2*xq + dx;
        int base = y*12 + x;

        long long acc0 = 0, acc1 = 0;
#pragma unroll 1
        for (int ch = 0; ch < 16; ch++) {
            float a = s_in[s_off[ch*32 + lane] + base];
            unsigned m = __ballot_sync(0xffffffffu, a != 0.f);
            if (ch == 15) m &= 0xFFFFFu;      // only 20 valid terms in last chunk
            while (m) {
                int bit = __ffs(m) - 1;
                m &= m - 1;
                const long long* wp = g_w2ll + (ch*32 + bit)*64;
                acc0 += __ldg(wp + lane);
                acc1 += __ldg(wp + lane + 32);
            }
        }
        float inp0 = __fmul_rn(10.0f, __fadd_rn(fx2f(acc0), bias0));
        float inp1 = __fmul_rn(10.0f, __fadd_rn(fx2f(acc1), bias1));

        int sidx = (b*64 + y*8 + x)*64 + lane;
        float v0 = g_v1[sidx],      i0 = g_i1[sidx];
        float v1 = g_v1[sidx + 32], i1 = g_i1[sidx + 32];
        float z0, z1;
        lif_update(v0, i0, inp0, z0);
        lif_update(v1, i1, inp1, z1);
        g_v1[sidx] = v0;      g_i1[sidx] = i0;
        g_v1[sidx + 32] = v1; g_i1[sidx + 32] = i1;
        z0max = fmaxf(z0max, z0);
        z1max = fmaxf(z1max, z1);
    }

    int pos = yp*4 + xq;
    g_sp1[b*800 + co*16 + pos] = z0max;
    if (co2 < 50) g_sp1[b*800 + co2*16 + pos] = z1max;
}

// ---------------- K3: FC 800->500 + LIF2 + readout 500->10 + LI (fused) -----
__global__ __launch_bounds__(512) void k_fc_out(
    const float* __restrict__ b_fc, float* __restrict__ volt, int t)
{
    __shared__ float sz[512];
    int b = blockIdx.x, tid = threadIdx.x;
    int lane = tid & 31;
    int m = tid;                 // one FC neuron per thread (m<500 real)

    long long acc = 0;
    const float* spb = g_sp1 + b*800;
#pragma unroll 1
    for (int ch = 0; ch < 25; ch++) {
        float a = __ldg(spb + ch*32 + lane);
        unsigned msk = __ballot_sync(0xffffffffu, a != 0.f);
        while (msk) {
            int bit = __ffs(msk) - 1;
            msk &= msk - 1;
            acc += __ldg(&g_wfcll[(ch*32 + bit)*512 + m]);
        }
    }
    float bias = (m < 500) ? __ldg(&b_fc[m]) : 0.f;
    float inp = __fadd_rn(fx2f(acc), bias);

    int sidx = b*512 + m;
    float v = g_v2[sidx], ii = g_i2[sidx];
    float z;
    lif_update(v, ii, inp, z);
    g_v2[sidx] = v;
    g_i2[sidx] = ii;
    sz[m] = (m < 500) ? z : 0.f;
    __syncthreads();

    // readout: warp w (<10) computes output w; exact int64 sum of selected w_out
    int w = tid >> 5;
    if (w < 10) {
        long long ao = 0;
        const long long* wr = g_woutll + w*500;
#pragma unroll 1
        for (int j = lane; j < 500; j += 32)
            if (sz[j] != 0.f) ao += __ldg(wr + j);
#pragma unroll
        for (int off = 16; off; off >>= 1)
            ao += __shfl_xor_sync(0xffffffffu, ao, off);
        if (lane == 0) {
            float sum = fx2f(ao);
            int idx = b*10 + w;
            float vo = g_vo[idx], io = g_io[idx];
            float vn = __fadd_rn(vo, __fmul_rn(LIF_BETA, __fsub_rn(io, vo)));
            g_vo[idx] = vn;
            g_io[idx] = __fadd_rn(__fmul_rn(LIF_IDEC, io), sum);
            volt[((size_t)t * BATCH + b)*10 + w] = vn;
        }
    }
}

// ---------------- launch -----------------------------------------------------
extern "C" void kernel_launch(void* const* d_in, const int* in_sizes, int n_in,
                              void* d_out, int out_size)
{
    const float* x     = (const float*)d_in[0];
    const float* w1    = (const float*)d_in[1];
    const float* b1    = (const float*)d_in[2];
    const float* w2    = (const float*)d_in[3];
    const float* b2    = (const float*)d_in[4];
    const float* w_fc  = (const float*)d_in[5];
    const float* b_fc  = (const float*)d_in[6];
    const float* w_out = (const float*)d_in[7];
    float* volt = (float*)d_out;

    zero_states<<<(BATCH*20*24*24 + 255)/256, 256>>>();
    prep_weights<<<(800*512 + 255)/256, 256>>>(w2, w_fc, w_out);

    for (int t = 0; t < TSTEPS; t++) {
        dim3 g1(BATCH, 20);
        k_conv1<<<g1, 160>>>(x, w1, b1, t);
        k_conv2<<<BATCH, 512>>>(b2);
        k_fc_out<<<BATCH, 512>>>(b_fc, volt, t);
    }
}

// round 6
// speedup vs baseline: 6.0287x; 1.0197x over previous
#include <cuda_runtime.h>

#define BATCH 256
#define TSTEPS 64

#define SCALE_F  4503599627370496.0f      // 2^52
#define INV_SCALE 2.220446049250313e-16   // 2^-52 (double)

// ---------------- persistent state (device globals; no allocation) ----------
__device__ float g_c1[(size_t)TSTEPS*BATCH*20*576];  // conv1+bias, all timesteps
__device__ float g_v0[BATCH*20*576];
__device__ float g_i0[BATCH*20*576];
__device__ float g_v1[BATCH*64*64];       // [b][pos(8x8)][co padded to 64]
__device__ float g_i1[BATCH*64*64];
__device__ float g_v2[BATCH*512];         // [b][m padded to 512]
__device__ float g_i2[BATCH*512];
__device__ float g_vo[BATCH*10];
__device__ float g_io[BATCH*10];
__device__ long long g_w2ll[512*64];      // conv2 w * 2^52, [t pad 512][co pad 64]
__device__ long long g_wfcll[800*512];    // fc w * 2^52, [k][m pad 512]
__device__ long long g_woutll[10*500];    // w_out * 2^52

#define LIF_BETA 0.1f
#define LIF_IDEC 0.8f
#define LIF_VTH  1.0f

// LIF update with STRICT per-op rounding (no FMA contraction):
__device__ __forceinline__ void lif_update(float& v, float& i, float inp, float& z)
{
    float vd = __fadd_rn(v, __fmul_rn(LIF_BETA, __fsub_rn(i, v)));
    z = (vd > LIF_VTH) ? 1.f : 0.f;
    v = __fmul_rn(__fsub_rn(1.f, z), vd);
    i = __fadd_rn(__fmul_rn(LIF_IDEC, i), inp);
}

__device__ __forceinline__ float fx2f(long long acc)
{
    return (float)((double)acc * INV_SCALE);
}

// ---------------- setup kernels ---------------------------------------------
__global__ void zero_states() {
    int i = blockIdx.x * blockDim.x + threadIdx.x;
    if (i < BATCH*20*576) { g_v0[i] = 0.f; g_i0[i] = 0.f; }
    if (i < BATCH*64*64)  { g_v1[i] = 0.f; g_i1[i] = 0.f; }
    if (i < BATCH*512)    { g_v2[i] = 0.f; g_i2[i] = 0.f; }
    if (i < BATCH*10)     { g_vo[i] = 0.f; g_io[i] = 0.f; }
}

__global__ void prep_weights(const float* __restrict__ w2,
                             const float* __restrict__ w_fc,
                             const float* __restrict__ w_out) {
    int i = blockIdx.x * blockDim.x + threadIdx.x;
    if (i < 512*64) {                 // conv2: [t][co], t = ci*25+k
        int t = i >> 6, co = i & 63;
        float w = (t < 500 && co < 50) ? w2[co*500 + t] : 0.f;
        g_w2ll[i] = __float2ll_rn(__fmul_rn(w, SCALE_F));
    }
    if (i < 800*512) {                // fc transpose: [k][m]
        int k = i >> 9, m = i & 511;
        float w = (m < 500) ? w_fc[m*800 + k] : 0.f;
        g_wfcll[i] = __float2ll_rn(__fmul_rn(w, SCALE_F));
    }
    if (i < 10*500) {
        g_woutll[i] = __float2ll_rn(__fmul_rn(w_out[i], SCALE_F));
    }
}

// ---------------- K1: conv1 for ALL timesteps (state-independent) -----------
// grid (B*T, 20), block 160. Thread = one pooled quad (2x2 of 24x24).
// Exact accumulation: TwoProdFMA -> int64 fixed point @ 2^-52 (bit-identical
// to the sequential version). Stores inp = (float)sum + bias.
__global__ __launch_bounds__(160) void k_conv1_all(
    const float* __restrict__ x, const float* __restrict__ w1,
    const float* __restrict__ b1)
{
    __shared__ float sx[784];
    __shared__ float sw[25];
    int tb = blockIdx.x;              // t*BATCH + b
    int cch = blockIdx.y;
    int tid = threadIdx.x;
    const float* xp = x + (size_t)tb * 784;
    for (int i = tid; i < 784; i += 160) sx[i] = xp[i];
    if (tid < 25) sw[tid] = w1[cch*25 + tid];
    __syncthreads();
    if (tid >= 144) return;

    int yp = tid / 12, xq = tid % 12;
    int y0 = 2*yp, x0 = 2*xq;

    float in[6][6];
#pragma unroll
    for (int i = 0; i < 6; i++)
#pragma unroll
        for (int j = 0; j < 6; j++)
            in[i][j] = sx[(y0+i)*28 + x0 + j];

    long long a00 = 0, a01 = 0, a10 = 0, a11 = 0;
#pragma unroll
    for (int ki = 0; ki < 5; ki++)
#pragma unroll
        for (int kj = 0; kj < 5; kj++) {
            float w = sw[ki*5 + kj];
            {   float a = in[ki  ][kj  ];
                float p = __fmul_rn(a, w);
                float e = __fmaf_rn(a, w, -p);
                a00 += __float2ll_rn(__fmul_rn(p, SCALE_F))
                     + __float2ll_rn(__fmul_rn(e, SCALE_F)); }
            {   float a = in[ki  ][kj+1];
                float p = __fmul_rn(a, w);
                float e = __fmaf_rn(a, w, -p);
                a01 += __float2ll_rn(__fmul_rn(p, SCALE_F))
                     + __float2ll_rn(__fmul_rn(e, SCALE_F)); }
            {   float a = in[ki+1][kj  ];
                float p = __fmul_rn(a, w);
                float e = __fmaf_rn(a, w, -p);
                a10 += __float2ll_rn(__fmul_rn(p, SCALE_F))
                     + __float2ll_rn(__fmul_rn(e, SCALE_F)); }
            {   float a = in[ki+1][kj+1];
                float p = __fmul_rn(a, w);
                float e = __fmaf_rn(a, w, -p);
                a11 += __float2ll_rn(__fmul_rn(p, SCALE_F))
                     + __float2ll_rn(__fmul_rn(e, SCALE_F)); }
        }

    float bias = __ldg(&b1[cch]);
    float* outp = g_c1 + ((size_t)tb*20 + cch)*576;
    float2 r0 = make_float2(__fadd_rn(fx2f(a00), bias), __fadd_rn(fx2f(a01), bias));
    float2 r1 = make_float2(__fadd_rn(fx2f(a10), bias), __fadd_rn(fx2f(a11), bias));
    *(float2*)&outp[ y0   *24 + x0] = r0;
    *(float2*)&outp[(y0+1)*24 + x0] = r1;
}

// ---------------- K2: fused per-timestep network step -----------------------
// Block = one sample (512 thr, 16 warps). One launch per timestep.
//  A: LIF0 + 2x2 maxpool (from precomputed conv1)  -> s_in[2880]
//  B: sparse conv2 (int64 exact) + LIF1 + maxpool  -> s_sp1[800]
//  C: sparse FC (int64 exact) + LIF2               -> s_z2[512]
//  D: readout (int64 exact) + LI                   -> volt
__global__ __launch_bounds__(512) void k_step(
    const float* __restrict__ b2, const float* __restrict__ b_fc,
    float* __restrict__ volt, int t)
{
    __shared__ float s_in[2880];
    __shared__ int   s_off[512];
    __shared__ float s_sp1[800];
    __shared__ float s_z2[512];

    int b = blockIdx.x, tid = threadIdx.x;
    int lane = tid & 31;

    // ---- Phase A: LIF0 + pool ----
    {
        const float* c1 = g_c1 + ((size_t)t*BATCH + b)*11520;
        float* v0p = g_v0 + b*11520;
        float* i0p = g_i0 + b*11520;
        for (int q = tid; q < 2880; q += 512) {
            int c = q / 144, rr = q % 144;
            int r = rr / 12, xx = rr % 12;
            int base = (c*24 + 2*r)*24 + 2*xx;
            float zmax = 0.f;
#pragma unroll
            for (int dy = 0; dy < 2; dy++) {
                int idx = base + dy*24;
                float2 inp = *(const float2*)&c1[idx];
                float2 v  = *(float2*)&v0p[idx];
                float2 ii = *(float2*)&i0p[idx];
                float z0, z1;
                lif_update(v.x, ii.x, inp.x, z0);
                lif_update(v.y, ii.y, inp.y, z1);
                *(float2*)&v0p[idx] = v;
                *(float2*)&i0p[idx] = ii;
                zmax = fmaxf(zmax, fmaxf(z0, z1));
            }
            s_in[q] = zmax;
        }
        int tt = (tid < 500) ? tid : 0;
        int ci = tt / 25, k = tt % 25;
        s_off[tid] = ci*144 + (k/5)*12 + (k%5);
    }
    __syncthreads();

    // ---- Phase B: conv2 + LIF1 + pool ----
    {
        int warp = tid >> 5;
        int yp = warp >> 2, xq = warp & 3;
        int co = lane, co2 = lane + 32;
        float bias0 = __ldg(&b2[co]);
        float bias1 = (co2 < 50) ? __ldg(&b2[co2]) : 0.f;
        float z0max = 0.f, z1max = 0.f;

#pragma unroll
        for (int sp = 0; sp < 4; sp++) {
            int dy = sp >> 1, dx = sp & 1;
            int y = 2*yp + dy, x = 2*xq + dx;
            int base = y*12 + x;

            long long acc0 = 0, acc1 = 0;
#pragma unroll 1
            for (int ch = 0; ch < 16; ch++) {
                float a = s_in[s_off[ch*32 + lane] + base];
                unsigned m = __ballot_sync(0xffffffffu, a != 0.f);
                if (ch == 15) m &= 0xFFFFFu;
                while (m) {
                    int bit = __ffs(m) - 1;
                    m &= m - 1;
                    const long long* wp = g_w2ll + (ch*32 + bit)*64;
                    acc0 += __ldg(wp + lane);
                    acc1 += __ldg(wp + lane + 32);
                }
            }
            float inp0 = __fmul_rn(10.0f, __fadd_rn(fx2f(acc0), bias0));
            float inp1 = __fmul_rn(10.0f, __fadd_rn(fx2f(acc1), bias1));

            int sidx = (b*64 + y*8 + x)*64 + lane;
            float v0 = g_v1[sidx],      i0 = g_i1[sidx];
            float v1 = g_v1[sidx + 32], i1 = g_i1[sidx + 32];
            float z0, z1;
            lif_update(v0, i0, inp0, z0);
            lif_update(v1, i1, inp1, z1);
            g_v1[sidx] = v0;      g_i1[sidx] = i0;
            g_v1[sidx + 32] = v1; g_i1[sidx + 32] = i1;
            z0max = fmaxf(z0max, z0);
            z1max = fmaxf(z1max, z1);
        }
        int pos = yp*4 + xq;
        s_sp1[co*16 + pos] = z0max;
        if (co2 < 50) s_sp1[co2*16 + pos] = z1max;
    }
    __syncthreads();

    // ---- Phase C: FC + LIF2 ----
    {
        int m = tid;
        long long acc = 0;
#pragma unroll 1
        for (int ch = 0; ch < 25; ch++) {
            float a = s_sp1[ch*32 + lane];
            unsigned msk = __ballot_sync(0xffffffffu, a != 0.f);
            while (msk) {
                int bit = __ffs(msk) - 1;
                msk &= msk - 1;
                acc += __ldg(&g_wfcll[(ch*32 + bit)*512 + m]);
            }
        }
        float bias = (m < 500) ? __ldg(&b_fc[m]) : 0.f;
        float inp = __fadd_rn(fx2f(acc), bias);

        int sidx = b*512 + m;
        float v = g_v2[sidx], ii = g_i2[sidx];
        float z;
        lif_update(v, ii, inp, z);
        g_v2[sidx] = v;
        g_i2[sidx] = ii;
        s_z2[m] = (m < 500) ? z : 0.f;
    }
    __syncthreads();

    // ---- Phase D: readout + LI ----
    {
        int w = tid >> 5;
        if (w < 10) {
            long long ao = 0;
            const long long* wr = g_woutll + w*500;
#pragma unroll 1
            for (int j = lane; j < 500; j += 32)
                if (s_z2[j] != 0.f) ao += __ldg(wr + j);
#pragma unroll
            for (int off = 16; off; off >>= 1)
                ao += __shfl_xor_sync(0xffffffffu, ao, off);
            if (lane == 0) {
                float sum = fx2f(ao);
                int idx = b*10 + w;
                float vo = g_vo[idx], io = g_io[idx];
                float vn = __fadd_rn(vo, __fmul_rn(LIF_BETA, __fsub_rn(io, vo)));
                g_vo[idx] = vn;
                g_io[idx] = __fadd_rn(__fmul_rn(LIF_IDEC, io), sum);
                volt[((size_t)t * BATCH + b)*10 + w] = vn;
            }
        }
    }
}

// ---------------- launch -----------------------------------------------------
extern "C" void kernel_launch(void* const* d_in, const int* in_sizes, int n_in,
                              void* d_out, int out_size)
{
    const float* x     = (const float*)d_in[0];
    const float* w1    = (const float*)d_in[1];
    const float* b1    = (const float*)d_in[2];
    const float* w2    = (const float*)d_in[3];
    const float* b2    = (const float*)d_in[4];
    const float* w_fc  = (const float*)d_in[5];
    const float* b_fc  = (const float*)d_in[6];
    const float* w_out = (const float*)d_in[7];
    float* volt = (float*)d_out;

    zero_states<<<(BATCH*20*576 + 255)/256, 256>>>();
    prep_weights<<<(800*512 + 255)/256, 256>>>(w2, w_fc, w_out);

    dim3 gc1(BATCH*TSTEPS, 20);
    k_conv1_all<<<gc1, 160>>>(x, w1, b1);

    for (int t = 0; t < TSTEPS; t++)
        k_step<<<BATCH, 512>>>(b2, b_fc, volt, t);
}

// round 7
// speedup vs baseline: 17.7441x; 2.9433x over previous
#include <cuda_runtime.h>

#define BATCH 256
#define TSTEPS 64

// ---------------- persistent state (device globals; no allocation) ----------
__device__ float g_c1[(size_t)TSTEPS*BATCH*20*576];  // conv1+bias, all timesteps
__device__ float g_v0[BATCH*20*576];
__device__ float g_i0[BATCH*20*576];
__device__ float g_v1[BATCH*64*64];       // [b][pos(8x8)][co padded to 64]
__device__ float g_i1[BATCH*64*64];
__device__ float g_v2[BATCH*512];         // [b][m padded to 512]
__device__ float g_i2[BATCH*512];
__device__ float g_vo[BATCH*10];
__device__ float g_io[BATCH*10];
__device__ long long g_w2ll[512*64];      // conv2 w * 2^52, [t pad 512][co pad 64]
__device__ long long g_wfcll[800*512];    // fc w * 2^52, [k][m pad 512]
__device__ long long g_woutll[10*500];    // w_out * 2^52

#define LIF_BETA 0.1f
#define LIF_IDEC 0.8f
#define LIF_VTH  1.0f

#define SCALE52_F 4503599627370496.0f     // 2^52
#define INV52_D   2.220446049250313e-16   // 2^-52
#define MAGIC_F   12582912.0f             // 1.5 * 2^23
#define MAGIC_I   0x4B400000

// LIF update with STRICT per-op rounding (no FMA contraction):
__device__ __forceinline__ void lif_update(float& v, float& i, float inp, float& z)
{
    float vd = __fadd_rn(v, __fmul_rn(LIF_BETA, __fsub_rn(i, v)));
    z = (vd > LIF_VTH) ? 1.f : 0.f;
    v = __fmul_rn(__fsub_rn(1.f, z), vd);
    i = __fadd_rn(__fmul_rn(LIF_IDEC, i), inp);
}

__device__ __forceinline__ float fx2f(long long acc)
{
    return (float)((double)acc * INV52_D);
}

// Exact product accumulation on full-rate pipes only.
// p (exact) -> limbs at grids 2^-18 (A0) and 2^-40 (A1), fp32 tail R @2^-40.
// e (exact FMA residual, |e|<=2^-20) -> limb at 2^-42 (A2), fp32 tail Re @2^-42.
// Magic-number rne: valid for |P|<2^22 (|p|<=16, |r1|<=0.5, |e·2^42|<=2^22).
__device__ __forceinline__ void acc_prod(float a, float w,
    int& A0, int& A1, int& A2, float& R, float& Re)
{
    float p  = __fmul_rn(a, w);
    float e  = __fmaf_rn(a, w, -p);
    float P1 = __fmul_rn(p, 262144.0f);            // 2^18
    float t1 = __fadd_rn(P1, MAGIC_F);
    int   h  = __float_as_int(t1) - MAGIC_I;
    float hf = __fsub_rn(t1, MAGIC_F);
    float r1 = __fsub_rn(P1, hf);                  // exact, |r1|<=0.5
    float P2 = __fmul_rn(r1, 4194304.0f);          // 2^22
    float t2 = __fadd_rn(P2, MAGIC_F);
    int   m  = __float_as_int(t2) - MAGIC_I;
    float mf = __fsub_rn(t2, MAGIC_F);
    float r2 = __fsub_rn(P2, mf);                  // exact, |r2|<=0.5
    float E1 = __fmul_rn(e, 4398046511104.0f);     // 2^42
    float t3 = __fadd_rn(E1, MAGIC_F);
    int   g  = __float_as_int(t3) - MAGIC_I;
    float gf = __fsub_rn(t3, MAGIC_F);
    float re = __fsub_rn(E1, gf);                  // exact, |re|<=0.5
    A0 += h; A1 += m; A2 += g;
    R  = __fadd_rn(R, r2);
    Re = __fadd_rn(Re, re);
}

// Combine limbs at unified grid 2^-42. |I| <= ~2^51 -> LL2D exact.
__device__ __forceinline__ float limb_final(int A0, int A1, int A2, float R, float Re)
{
    long long I = ((long long)A0 << 24) + ((long long)A1 << 2) + (long long)A2;
    float T = __fmaf_rn(4.0f, R, Re);              // tails at 2^-42 units
    double D = ((double)I + (double)T) * 2.2737367544323206e-13;  // * 2^-42
    return (float)D;
}

// ---------------- setup kernels ---------------------------------------------
__global__ void zero_states() {
    int i = blockIdx.x * blockDim.x + threadIdx.x;
    if (i < BATCH*20*576) { g_v0[i] = 0.f; g_i0[i] = 0.f; }
    if (i < BATCH*64*64)  { g_v1[i] = 0.f; g_i1[i] = 0.f; }
    if (i < BATCH*512)    { g_v2[i] = 0.f; g_i2[i] = 0.f; }
    if (i < BATCH*10)     { g_vo[i] = 0.f; g_io[i] = 0.f; }
}

__global__ void prep_weights(const float* __restrict__ w2,
                             const float* __restrict__ w_fc,
                             const float* __restrict__ w_out) {
    int i = blockIdx.x * blockDim.x + threadIdx.x;
    if (i < 512*64) {                 // conv2: [t][co], t = ci*25+k
        int t = i >> 6, co = i & 63;
        float w = (t < 500 && co < 50) ? w2[co*500 + t] : 0.f;
        g_w2ll[i] = __float2ll_rn(__fmul_rn(w, SCALE52_F));
    }
    if (i < 800*512) {                // fc transpose: [k][m]
        int k = i >> 9, m = i & 511;
        float w = (m < 500) ? w_fc[m*800 + k] : 0.f;
        g_wfcll[i] = __float2ll_rn(__fmul_rn(w, SCALE52_F));
    }
    if (i < 10*500) {
        g_woutll[i] = __float2ll_rn(__fmul_rn(w_out[i], SCALE52_F));
    }
}

// ---------------- K1: conv1 for ALL timesteps (state-independent) -----------
// grid (B*T, 20), block 160. Thread = one pooled quad (2x2 of 24x24).
// Near-exact limb accumulation (error ~2^-60 abs + 2^-53 rel final round).
__global__ __launch_bounds__(160) void k_conv1_all(
    const float* __restrict__ x, const float* __restrict__ w1,
    const float* __restrict__ b1)
{
    __shared__ float sx[784];
    __shared__ float sw[25];
    __shared__ int   skoff[25];
    int tb = blockIdx.x;              // t*BATCH + b
    int cch = blockIdx.y;
    int tid = threadIdx.x;
    const float* xp = x + (size_t)tb * 784;
    for (int i = tid; i < 784; i += 160) sx[i] = xp[i];
    if (tid < 25) {
        sw[tid] = w1[cch*25 + tid];
        skoff[tid] = (tid/5)*28 + (tid%5);
    }
    __syncthreads();
    if (tid >= 144) return;

    int yp = tid / 12, xq = tid % 12;
    int base00 = (2*yp)*28 + 2*xq;

    int A0[4] = {0,0,0,0}, A1[4] = {0,0,0,0}, A2[4] = {0,0,0,0};
    float R[4] = {0,0,0,0}, Re[4] = {0,0,0,0};

#pragma unroll 5
    for (int k25 = 0; k25 < 25; k25++) {
        float w = sw[k25];
        int o = base00 + skoff[k25];
        float a00 = sx[o],      a01 = sx[o + 1];
        float a10 = sx[o + 28], a11 = sx[o + 29];
        acc_prod(a00, w, A0[0], A1[0], A2[0], R[0], Re[0]);
        acc_prod(a01, w, A0[1], A1[1], A2[1], R[1], Re[1]);
        acc_prod(a10, w, A0[2], A1[2], A2[2], R[2], Re[2]);
        acc_prod(a11, w, A0[3], A1[3], A2[3], R[3], Re[3]);
    }

    float bias = __ldg(&b1[cch]);
    float s00 = __fadd_rn(limb_final(A0[0], A1[0], A2[0], R[0], Re[0]), bias);
    float s01 = __fadd_rn(limb_final(A0[1], A1[1], A2[1], R[1], Re[1]), bias);
    float s10 = __fadd_rn(limb_final(A0[2], A1[2], A2[2], R[2], Re[2]), bias);
    float s11 = __fadd_rn(limb_final(A0[3], A1[3], A2[3], R[3], Re[3]), bias);

    float* outp = g_c1 + ((size_t)tb*20 + cch)*576;
    *(float2*)&outp[(2*yp  )*24 + 2*xq] = make_float2(s00, s01);
    *(float2*)&outp[(2*yp+1)*24 + 2*xq] = make_float2(s10, s11);
}

// ---------------- K2: ALL 64 timesteps, persistent (samples independent) ----
// grid 128, block 1024 = two independent 512-thread halves (one sample each).
// Per t: A) LIF0+pool  B) sparse conv2+LIF1+pool  C) sparse FC+LIF2  D) readout+LI
__global__ __launch_bounds__(1024) void k_steps(
    const float* __restrict__ b2, const float* __restrict__ b_fc,
    float* __restrict__ volt)
{
    __shared__ float s_in[2][2880];
    __shared__ int   s_off[512];
    __shared__ float s_sp1[2][800];
    __shared__ float s_z2[2][512];

    int half = threadIdx.x >> 9;
    int tid  = threadIdx.x & 511;
    int b    = blockIdx.x*2 + half;
    int lane = tid & 31;
    int warp = tid >> 5;              // 0..15 within half

    if (threadIdx.x < 512) {
        int tt = (threadIdx.x < 500) ? (int)threadIdx.x : 0;
        int ci = tt / 25, k = tt % 25;
        s_off[threadIdx.x] = ci*144 + (k/5)*12 + (k%5);
    }

    // hoisted per-thread constants
    int yp = warp >> 2, xq = warp & 3;
    int co = lane, co2 = lane + 32;
    float bias0 = __ldg(&b2[co]);
    float bias1 = (co2 < 50) ? __ldg(&b2[co2]) : 0.f;
    float biasf = (tid < 500) ? __ldg(&b_fc[tid]) : 0.f;
    float* v0p = g_v0 + b*11520;
    float* i0p = g_i0 + b*11520;

    __syncthreads();

    for (int t = 0; t < TSTEPS; t++) {
        // ---- Phase A: LIF0 + pool ----
        {
            const float* c1 = g_c1 + ((size_t)t*BATCH + b)*11520;
            for (int q = tid; q < 2880; q += 512) {
                int c = q / 144, rr = q % 144;
                int r = rr / 12, xx = rr % 12;
                int base = (c*24 + 2*r)*24 + 2*xx;
                float zmax = 0.f;
#pragma unroll
                for (int dy = 0; dy < 2; dy++) {
                    int idx = base + dy*24;
                    float2 inp = *(const float2*)&c1[idx];
                    float2 v  = *(float2*)&v0p[idx];
                    float2 ii = *(float2*)&i0p[idx];
                    float z0, z1;
                    lif_update(v.x, ii.x, inp.x, z0);
                    lif_update(v.y, ii.y, inp.y, z1);
                    *(float2*)&v0p[idx] = v;
                    *(float2*)&i0p[idx] = ii;
                    zmax = fmaxf(zmax, fmaxf(z0, z1));
                }
                s_in[half][q] = zmax;
            }
        }
        __syncthreads();

        // ---- Phase B: conv2 + LIF1 + pool ----
        {
            float z0max = 0.f, z1max = 0.f;
#pragma unroll
            for (int sp = 0; sp < 4; sp++) {
                int dy = sp >> 1, dx = sp & 1;
                int y = 2*yp + dy, x = 2*xq + dx;
                int base = y*12 + x;

                long long acc0 = 0, acc1 = 0;
#pragma unroll 1
                for (int ch = 0; ch < 16; ch++) {
                    float a = s_in[half][s_off[ch*32 + lane] + base];
                    unsigned m = __ballot_sync(0xffffffffu, a != 0.f);
                    if (ch == 15) m &= 0xFFFFFu;
                    while (m) {
                        int bit = __ffs(m) - 1;
                        m &= m - 1;
                        const long long* wp = g_w2ll + (ch*32 + bit)*64;
                        acc0 += __ldg(wp + lane);
                        acc1 += __ldg(wp + lane + 32);
                    }
                }
                float inp0 = __fmul_rn(10.0f, __fadd_rn(fx2f(acc0), bias0));
                float inp1 = __fmul_rn(10.0f, __fadd_rn(fx2f(acc1), bias1));

                int sidx = (b*64 + y*8 + x)*64 + lane;
                float v0 = g_v1[sidx],      i0 = g_i1[sidx];
                float v1 = g_v1[sidx + 32], i1 = g_i1[sidx + 32];
                float z0, z1;
                lif_update(v0, i0, inp0, z0);
                lif_update(v1, i1, inp1, z1);
                g_v1[sidx] = v0;      g_i1[sidx] = i0;
                g_v1[sidx + 32] = v1; g_i1[sidx + 32] = i1;
                z0max = fmaxf(z0max, z0);
                z1max = fmaxf(z1max, z1);
            }
            int pos = yp*4 + xq;
            s_sp1[half][co*16 + pos] = z0max;
            if (co2 < 50) s_sp1[half][co2*16 + pos] = z1max;
        }
        __syncthreads();

        // ---- Phase C: FC + LIF2 ----
        {
            int m = tid;
            long long acc = 0;
#pragma unroll 1
            for (int ch = 0; ch < 25; ch++) {
                float a = s_sp1[half][ch*32 + lane];
                unsigned msk = __ballot_sync(0xffffffffu, a != 0.f);
                while (msk) {
                    int bit = __ffs(msk) - 1;
                    msk &= msk - 1;
                    acc += __ldg(&g_wfcll[(ch*32 + bit)*512 + m]);
                }
            }
            float inp = __fadd_rn(fx2f(acc), biasf);

            int sidx = b*512 + m;
            float v = g_v2[sidx], ii = g_i2[sidx];
            float z;
            lif_update(v, ii, inp, z);
            g_v2[sidx] = v;
            g_i2[sidx] = ii;
            s_z2[half][m] = (m < 500) ? z : 0.f;
        }
        __syncthreads();

        // ---- Phase D: readout + LI ----
        if (warp < 10) {
            long long ao = 0;
            const long long* wr = g_woutll + warp*500;
#pragma unroll 1
            for (int j = lane; j < 500; j += 32)
                if (s_z2[half][j] != 0.f) ao += __ldg(wr + j);
#pragma unroll
            for (int off = 16; off; off >>= 1)
                ao += __shfl_xor_sync(0xffffffffu, ao, off);
            if (lane == 0) {
                float sum = fx2f(ao);
                int idx = b*10 + warp;
                float vo = g_vo[idx], io = g_io[idx];
                float vn = __fadd_rn(vo, __fmul_rn(LIF_BETA, __fsub_rn(io, vo)));
                g_vo[idx] = vn;
                g_io[idx] = __fadd_rn(__fmul_rn(LIF_IDEC, io), sum);
                volt[((size_t)t * BATCH + b)*10 + warp] = vn;
            }
        }
        __syncthreads();
    }
}

// ---------------- launch -----------------------------------------------------
extern "C" void kernel_launch(void* const* d_in, const int* in_sizes, int n_in,
                              void* d_out, int out_size)
{
    const float* x     = (const float*)d_in[0];
    const float* w1    = (const float*)d_in[1];
    const float* b1    = (const float*)d_in[2];
    const float* w2    = (const float*)d_in[3];
    const float* b2    = (const float*)d_in[4];
    const float* w_fc  = (const float*)d_in[5];
    const float* b_fc  = (const float*)d_in[6];
    const float* w_out = (const float*)d_in[7];
    float* volt = (float*)d_out;

    zero_states<<<(BATCH*20*576 + 255)/256, 256>>>();
    prep_weights<<<(800*512 + 255)/256, 256>>>(w2, w_fc, w_out);

    dim3 gc1(BATCH*TSTEPS, 20);
    k_conv1_all<<<gc1, 160>>>(x, w1, b1);

    k_steps<<<BATCH/2, 1024>>>(b2, b_fc, volt);
}

// round 9
// speedup vs baseline: 20.5281x; 1.1569x over previous
#include <cuda_runtime.h>

#define BATCH 256
#define TSTEPS 64

// ---------------- persistent state (device globals; no allocation) ----------
__device__ float g_c1[(size_t)TSTEPS*BATCH*20*576];  // conv1+bias, all timesteps
__device__ float g_v0[BATCH*20*576];
__device__ float g_i0[BATCH*20*576];
__device__ float g_v1[BATCH*64*64];       // [b][pos(8x8)][co padded to 64]
__device__ float g_i1[BATCH*64*64];
__device__ float g_v2[BATCH*512];         // [b][m padded to 512]
__device__ float g_i2[BATCH*512];
__device__ float g_vo[BATCH*10];
__device__ float g_io[BATCH*10];
__device__ long long g_w2ll[512*64];      // conv2 w * 2^52, [t pad 512][co pad 64]
__device__ long long g_wfcll[800*512];    // fc w * 2^52, [k][m pad 512]
__device__ long long g_woutll[10*500];    // w_out * 2^52

#define LIF_BETA 0.1f
#define LIF_IDEC 0.8f
#define LIF_VTH  1.0f

#define SCALE52_F 4503599627370496.0f     // 2^52
#define INV52_D   2.220446049250313e-16   // 2^-52
#define MAGIC_F   12582912.0f             // 1.5 * 2^23
#define MAGIC_I   0x4B400000

// LIF update with STRICT per-op rounding (no FMA contraction):
__device__ __forceinline__ void lif_update(float& v, float& i, float inp, float& z)
{
    float vd = __fadd_rn(v, __fmul_rn(LIF_BETA, __fsub_rn(i, v)));
    z = (vd > LIF_VTH) ? 1.f : 0.f;
    v = __fmul_rn(__fsub_rn(1.f, z), vd);
    i = __fadd_rn(__fmul_rn(LIF_IDEC, i), inp);
}

__device__ __forceinline__ float fx2f(long long acc)
{
    return (float)((double)acc * INV52_D);
}

// Near-exact product accumulation, ALL on full-rate fp32/alu pipes.
//   p = a*w (rounded), e = exact residual (TwoProdFMA).
//   p -> integer limbs A0 (grid 2^-18) and A1 (grid 2^-40) via magic-number
//   round-to-nearest; sub-2^-40 remainder dropped (|.|<=2^-41/product).
//   e accumulated in plain fp32 (|e|<=~6e-8; accumulation rounding ~1e-13).
__device__ __forceinline__ void acc_prod(float a, float w,
                                         int& A0, int& A1, float& Fe)
{
    float p  = __fmul_rn(a, w);
    float e  = __fmaf_rn(a, w, -p);
    float P1 = __fmul_rn(p, 262144.0f);            // 2^18, |P1| < 2^22
    float t1 = __fadd_rn(P1, MAGIC_F);
    int   h  = __float_as_int(t1) - MAGIC_I;
    float hf = __fsub_rn(t1, MAGIC_F);
    float r1 = __fsub_rn(P1, hf);                  // exact, |r1| <= 0.5
    float P2 = __fmul_rn(r1, 4194304.0f);          // 2^22 -> grid 2^-40, exact
    float t2 = __fadd_rn(P2, MAGIC_F);
    int   m  = __float_as_int(t2) - MAGIC_I;
    A0 += h; A1 += m;
    Fe = __fadd_rn(Fe, e);
}

// Combine limbs at grid 2^-40 + e-accumulator, pure fp32.
// I = A0*2^22 + A1 (units of 2^-40); split into exact <2^24 halves:
//   value = Ihi*2^24*2^-40 + Ilo*2^-40 = Ihi*2^-16 + Ilo*2^-40.
__device__ __forceinline__ float limb_final(int A0, int A1, float Fe)
{
    long long I = ((long long)A0 << 22) + (long long)A1;
    int Ihi = (int)(I >> 24);                      // |Ihi| <= ~2^23 (exact in f32)
    int Ilo = (int)(I & 0xFFFFFF);                 // [0, 2^24)     (exact in f32)
    float s = __fmaf_rn((float)Ilo, 9.094947017729282e-13f, Fe);   // 2^-40
    return __fmaf_rn((float)Ihi, 1.52587890625e-5f, s);            // 2^-16
}

// ---------------- setup kernels ---------------------------------------------
__global__ void zero_states() {
    int i = blockIdx.x * blockDim.x + threadIdx.x;
    if (i < BATCH*20*576) { g_v0[i] = 0.f; g_i0[i] = 0.f; }
    if (i < BATCH*64*64)  { g_v1[i] = 0.f; g_i1[i] = 0.f; }
    if (i < BATCH*512)    { g_v2[i] = 0.f; g_i2[i] = 0.f; }
    if (i < BATCH*10)     { g_vo[i] = 0.f; g_io[i] = 0.f; }
}

__global__ void prep_weights(const float* __restrict__ w2,
                             const float* __restrict__ w_fc,
                             const float* __restrict__ w_out) {
    int i = blockIdx.x * blockDim.x + threadIdx.x;
    if (i < 512*64) {                 // conv2: [t][co], t = ci*25+k
        int t = i >> 6, co = i & 63;
        float w = (t < 500 && co < 50) ? w2[co*500 + t] : 0.f;
        g_w2ll[i] = __float2ll_rn(__fmul_rn(w, SCALE52_F));
    }
    if (i < 800*512) {                // fc transpose: [k][m]
        int k = i >> 9, m = i & 511;
        float w = (m < 500) ? w_fc[m*800 + k] : 0.f;
        g_wfcll[i] = __float2ll_rn(__fmul_rn(w, SCALE52_F));
    }
    if (i < 10*500) {
        g_woutll[i] = __float2ll_rn(__fmul_rn(w_out[i], SCALE52_F));
    }
}

// ---------------- K1: conv1 for ALL timesteps (state-independent) -----------
// grid (B*T, 20), block 160. Thread = one pooled quad (2x2 of 24x24).
__global__ __launch_bounds__(160) void k_conv1_all(
    const float* __restrict__ x, const float* __restrict__ w1,
    const float* __restrict__ b1)
{
    __shared__ float sx[784];
    __shared__ float sw[25];
    __shared__ int   skoff[25];
    int tb = blockIdx.x;              // t*BATCH + b
    int cch = blockIdx.y;
    int tid = threadIdx.x;
    const float* xp = x + (size_t)tb * 784;
    for (int i = tid; i < 784; i += 160) sx[i] = xp[i];
    if (tid < 25) {
        sw[tid] = w1[cch*25 + tid];
        skoff[tid] = (tid/5)*28 + (tid%5);
    }
    __syncthreads();
    if (tid >= 144) return;

    int yp = tid / 12, xq = tid % 12;
    int base00 = (2*yp)*28 + 2*xq;

    int A0[4] = {0,0,0,0}, A1[4] = {0,0,0,0};
    float Fe[4] = {0,0,0,0};

#pragma unroll 5
    for (int k25 = 0; k25 < 25; k25++) {
        float w = sw[k25];
        int o = base00 + skoff[k25];
        float a00 = sx[o],      a01 = sx[o + 1];
        float a10 = sx[o + 28], a11 = sx[o + 29];
        acc_prod(a00, w, A0[0], A1[0], Fe[0]);
        acc_prod(a01, w, A0[1], A1[1], Fe[1]);
        acc_prod(a10, w, A0[2], A1[2], Fe[2]);
        acc_prod(a11, w, A0[3], A1[3], Fe[3]);
    }

    float bias = __ldg(&b1[cch]);
    float s00 = __fadd_rn(limb_final(A0[0], A1[0], Fe[0]), bias);
    float s01 = __fadd_rn(limb_final(A0[1], A1[1], Fe[1]), bias);
    float s10 = __fadd_rn(limb_final(A0[2], A1[2], Fe[2]), bias);
    float s11 = __fadd_rn(limb_final(A0[3], A1[3], Fe[3]), bias);

    float* outp = g_c1 + ((size_t)tb*20 + cch)*576;
    *(float2*)&outp[(2*yp  )*24 + 2*xq] = make_float2(s00, s01);
    *(float2*)&outp[(2*yp+1)*24 + 2*xq] = make_float2(s10, s11);
}

// ---------------- K2: ALL 64 timesteps, persistent (samples independent) ----
// grid 128, block 1024 = two independent 512-thread halves (one sample each).
__global__ __launch_bounds__(1024) void k_steps(
    const float* __restrict__ b2, const float* __restrict__ b_fc,
    float* __restrict__ volt)
{
    __shared__ float s_in[2][2880];
    __shared__ int   s_off[512];
    __shared__ float s_sp1[2][800];
    __shared__ float s_z2[2][512];

    int half = threadIdx.x >> 9;
    int tid  = threadIdx.x & 511;
    int b    = blockIdx.x*2 + half;
    int lane = tid & 31;
    int warp = tid >> 5;              // 0..15 within half

    if (threadIdx.x < 512) {
        int tt = (threadIdx.x < 500) ? (int)threadIdx.x : 0;
        int ci = tt / 25, k = tt % 25;
        s_off[threadIdx.x] = ci*144 + (k/5)*12 + (k%5);
    }

    int yp = warp >> 2, xq = warp & 3;
    int co = lane, co2 = lane + 32;
    float bias0 = __ldg(&b2[co]);
    float bias1 = (co2 < 50) ? __ldg(&b2[co2]) : 0.f;
    float biasf = (tid < 500) ? __ldg(&b_fc[tid]) : 0.f;
    float* v0p = g_v0 + b*11520;
    float* i0p = g_i0 + b*11520;

    __syncthreads();

    for (int t = 0; t < TSTEPS; t++) {
        // ---- Phase A: LIF0 + pool ----
        {
            const float* c1 = g_c1 + ((size_t)t*BATCH + b)*11520;
            for (int q = tid; q < 2880; q += 512) {
                int c = q / 144, rr = q % 144;
                int r = rr / 12, xx = rr % 12;
                int base = (c*24 + 2*r)*24 + 2*xx;
                float zmax = 0.f;
#pragma unroll
                for (int dy = 0; dy < 2; dy++) {
                    int idx = base + dy*24;
                    float2 inp = *(const float2*)&c1[idx];
                    float2 v  = *(float2*)&v0p[idx];
                    float2 ii = *(float2*)&i0p[idx];
                    float z0, z1;
                    lif_update(v.x, ii.x, inp.x, z0);
                    lif_update(v.y, ii.y, inp.y, z1);
                    *(float2*)&v0p[idx] = v;
                    *(float2*)&i0p[idx] = ii;
                    zmax = fmaxf(zmax, fmaxf(z0, z1));
                }
                s_in[half][q] = zmax;
            }
        }
        __syncthreads();

        // ---- Phase B: conv2 + LIF1 + pool ----
        {
            float z0max = 0.f, z1max = 0.f;
#pragma unroll
            for (int sp = 0; sp < 4; sp++) {
                int dy = sp >> 1, dx = sp & 1;
                int y = 2*yp + dy, x = 2*xq + dx;
                int base = y*12 + x;

                long long acc0 = 0, acc1 = 0;
#pragma unroll 1
                for (int ch = 0; ch < 16; ch++) {
                    float a = s_in[half][s_off[ch*32 + lane] + base];
                    unsigned m = __ballot_sync(0xffffffffu, a != 0.f);
                    if (ch == 15) m &= 0xFFFFFu;
                    while (m) {
                        int bit = __ffs(m) - 1;
                        m &= m - 1;
                        const long long* wp = g_w2ll + (ch*32 + bit)*64;
                        acc0 += __ldg(wp + lane);
                        acc1 += __ldg(wp + lane + 32);
                    }
                }
                float inp0 = __fmul_rn(10.0f, __fadd_rn(fx2f(acc0), bias0));
                float inp1 = __fmul_rn(10.0f, __fadd_rn(fx2f(acc1), bias1));

                int sidx = (b*64 + y*8 + x)*64 + lane;
                float v0 = g_v1[sidx],      i0 = g_i1[sidx];
                float v1 = g_v1[sidx + 32], i1 = g_i1[sidx + 32];
                float z0, z1;
                lif_update(v0, i0, inp0, z0);
                lif_update(v1, i1, inp1, z1);
                g_v1[sidx] = v0;      g_i1[sidx] = i0;
                g_v1[sidx + 32] = v1; g_i1[sidx + 32] = i1;
                z0max = fmaxf(z0max, z0);
                z1max = fmaxf(z1max, z1);
            }
            int pos = yp*4 + xq;
            s_sp1[half][co*16 + pos] = z0max;
            if (co2 < 50) s_sp1[half][co2*16 + pos] = z1max;
        }
        __syncthreads();

        // ---- Phase C: FC + LIF2 ----
        {
            int m = tid;
            long long acc = 0;
#pragma unroll 1
            for (int ch = 0; ch < 25; ch++) {
                float a = s_sp1[half][ch*32 + lane];
                unsigned msk = __ballot_sync(0xffffffffu, a != 0.f);
                while (msk) {
                    int bit = __ffs(msk) - 1;
                    msk &= msk - 1;
                    acc += __ldg(&g_wfcll[(ch*32 + bit)*512 + m]);
                }
            }
            float inp = __fadd_rn(fx2f(acc), biasf);

            int sidx = b*512 + m;
            float v = g_v2[sidx], ii = g_i2[sidx];
            float z;
            lif_update(v, ii, inp, z);
            g_v2[sidx] = v;
            g_i2[sidx] = ii;
            s_z2[half][m] = (m < 500) ? z : 0.f;
        }
        __syncthreads();

        // ---- Phase D: readout + LI ----
        if (warp < 10) {
            long long ao = 0;
            const long long* wr = g_woutll + warp*500;
#pragma unroll 1
            for (int j = lane; j < 500; j += 32)
                if (s_z2[half][j] != 0.f) ao += __ldg(wr + j);
#pragma unroll
            for (int off = 16; off; off >>= 1)
                ao += __shfl_xor_sync(0xffffffffu, ao, off);
            if (lane == 0) {
                float sum = fx2f(ao);
                int idx = b*10 + warp;
                float vo = g_vo[idx], io = g_io[idx];
                float vn = __fadd_rn(vo, __fmul_rn(LIF_BETA, __fsub_rn(io, vo)));
                g_vo[idx] = vn;
                g_io[idx] = __fadd_rn(__fmul_rn(LIF_IDEC, io), sum);
                volt[((size_t)t * BATCH + b)*10 + warp] = vn;
            }
        }
        __syncthreads();
    }
}

// ---------------- launch -----------------------------------------------------
extern "C" void kernel_launch(void* const* d_in, const int* in_sizes, int n_in,
                              void* d_out, int out_size)
{
    const float* x     = (const float*)d_in[0];
    const float* w1    = (const float*)d_in[1];
    const float* b1    = (const float*)d_in[2];
    const float* w2    = (const float*)d_in[3];
    const float* b2    = (const float*)d_in[4];
    const float* w_fc  = (const float*)d_in[5];
    const float* b_fc  = (const float*)d_in[6];
    const float* w_out = (const float*)d_in[7];
    float* volt = (float*)d_out;

    zero_states<<<(BATCH*20*576 + 255)/256, 256>>>();
    prep_weights<<<(800*512 + 255)/256, 256>>>(w2, w_fc, w_out);

    dim3 gc1(BATCH*TSTEPS, 20);
    k_conv1_all<<<gc1, 160>>>(x, w1, b1);

    k_steps<<<BATCH/2, 1024>>>(b2, b_fc, volt);
}

// round 10
// speedup vs baseline: 21.7930x; 1.0616x over previous
#include <cuda_runtime.h>

#define BATCH 256
#define TSTEPS 64

typedef unsigned long long u64;

// ---------------- persistent state (device globals; no allocation) ----------
__device__ float g_c1[(size_t)TSTEPS*BATCH*20*576];  // conv1+bias, all timesteps
__device__ float g_v0[BATCH*20*576];
__device__ float g_i0[BATCH*20*576];
__device__ float g_v1[BATCH*64*64];       // [b][pos(8x8)][co padded to 64]
__device__ float g_i1[BATCH*64*64];
__device__ float g_v2[BATCH*512];         // [b][m padded to 512]
__device__ float g_i2[BATCH*512];
__device__ float g_vo[BATCH*10];
__device__ float g_io[BATCH*10];
__device__ long long g_w2ll[512*64];      // conv2 w * 2^52, [t pad 512][co pad 64]
__device__ long long g_wfcll[800*512];    // fc w * 2^52, [k][m pad 512]
__device__ long long g_woutll[10*500];    // w_out * 2^52

#define LIF_BETA 0.1f
#define LIF_IDEC 0.8f
#define LIF_VTH  1.0f

#define SCALE52_F 4503599627370496.0f     // 2^52
#define INV52_D   2.220446049250313e-16   // 2^-52

// ---------------- packed f32x2 helpers (each = two independent IEEE f32 ops) -
__device__ __forceinline__ u64 pk2(float lo, float hi) {
    u64 r; asm("mov.b64 %0, {%1, %2};" : "=l"(r) : "f"(lo), "f"(hi)); return r;
}
__device__ __forceinline__ void upk2(u64 v, float& lo, float& hi) {
    asm("mov.b64 {%0, %1}, %2;" : "=f"(lo), "=f"(hi) : "l"(v));
}
__device__ __forceinline__ u64 mul2(u64 a, u64 b) {
    u64 r; asm("mul.rn.f32x2 %0, %1, %2;" : "=l"(r) : "l"(a), "l"(b)); return r;
}
__device__ __forceinline__ u64 add2(u64 a, u64 b) {
    u64 r; asm("add.rn.f32x2 %0, %1, %2;" : "=l"(r) : "l"(a), "l"(b)); return r;
}
__device__ __forceinline__ u64 fma2(u64 a, u64 b, u64 c) {
    u64 r; asm("fma.rn.f32x2 %0, %1, %2, %3;" : "=l"(r) : "l"(a), "l"(b), "l"(c)); return r;
}

// LIF update with STRICT per-op rounding (no FMA contraction):
__device__ __forceinline__ void lif_update(float& v, float& i, float inp, float& z)
{
    float vd = __fadd_rn(v, __fmul_rn(LIF_BETA, __fsub_rn(i, v)));
    z = (vd > LIF_VTH) ? 1.f : 0.f;
    v = __fmul_rn(__fsub_rn(1.f, z), vd);
    i = __fadd_rn(__fmul_rn(LIF_IDEC, i), inp);
}

__device__ __forceinline__ float fx2f(long long acc)
{
    return (float)((double)acc * INV52_D);
}

// ---------------- setup kernels ---------------------------------------------
__global__ void zero_states() {
    int i = blockIdx.x * blockDim.x + threadIdx.x;
    if (i < BATCH*20*576) { g_v0[i] = 0.f; g_i0[i] = 0.f; }
    if (i < BATCH*64*64)  { g_v1[i] = 0.f; g_i1[i] = 0.f; }
    if (i < BATCH*512)    { g_v2[i] = 0.f; g_i2[i] = 0.f; }
    if (i < BATCH*10)     { g_vo[i] = 0.f; g_io[i] = 0.f; }
}

__global__ void prep_weights(const float* __restrict__ w2,
                             const float* __restrict__ w_fc,
                             const float* __restrict__ w_out) {
    int i = blockIdx.x * blockDim.x + threadIdx.x;
    if (i < 512*64) {                 // conv2: [t][co], t = ci*25+k
        int t = i >> 6, co = i & 63;
        float w = (t < 500 && co < 50) ? w2[co*500 + t] : 0.f;
        g_w2ll[i] = __float2ll_rn(__fmul_rn(w, SCALE52_F));
    }
    if (i < 800*512) {                // fc transpose: [k][m]
        int k = i >> 9, m = i & 511;
        float w = (m < 500) ? w_fc[m*800 + k] : 0.f;
        g_wfcll[i] = __float2ll_rn(__fmul_rn(w, SCALE52_F));
    }
    if (i < 10*500) {
        g_woutll[i] = __float2ll_rn(__fmul_rn(w_out[i], SCALE52_F));
    }
}

// ---------------- K1: conv1 for ALL timesteps (state-independent) -----------
// grid (B*T, 20), block 160. Thread = one pooled quad (2x2 of 24x24), outputs
// processed as 2 packed f32x2 pairs (top row, bottom row).
//
// Near-exact sum via packed limb accumulation (all full-rate pipes):
//   p = a*w, e = exact FMA residual.
//   magic(48 = 1.5*2^5): hf = round(p to grid 2^-18) exact; Ah += hf is exact
//   (multiples of 2^-18, |sum|<64). r1 = p - hf exact (Sterbenz), |r1|<=2^-18;
//   Ar += r1 and Fe += e accumulate in fp32 with total rounding ~1e-12.
// Final: fl(Ah + fl(Ar + Fe)) = correctly-rounded exact sum +- ~1e-12.
__global__ __launch_bounds__(160) void k_conv1_all(
    const float* __restrict__ x, const float* __restrict__ w1,
    const float* __restrict__ b1)
{
    __shared__ float sx[784];
    __shared__ float sw[25];
    int tb = blockIdx.x;              // t*BATCH + b
    int cch = blockIdx.y;
    int tid = threadIdx.x;
    const float* xp = x + (size_t)tb * 784;
    for (int i = tid; i < 784; i += 160) sx[i] = xp[i];
    if (tid < 25) sw[tid] = w1[cch*25 + tid];
    __syncthreads();
    if (tid >= 144) return;

    int yp = tid / 12, xq = tid % 12;
    int y0 = 2*yp, x0 = 2*xq;

    float in[6][6];
#pragma unroll
    for (int i = 0; i < 6; i++)
#pragma unroll
        for (int j = 0; j < 6; j++)
            in[i][j] = sx[(y0+i)*28 + x0 + j];

    const u64 SGN  = 0x8000000080000000ULL;
    const u64 M18  = pk2(48.0f, 48.0f);            // 1.5*2^5 -> grid 2^-18
    const u64 nM18 = pk2(-48.0f, -48.0f);
    const u64 NEG1 = pk2(-1.0f, -1.0f);

    u64 AhT = 0, ArT = 0, FeT = 0;                 // top row (a00,a01)
    u64 AhB = 0, ArB = 0, FeB = 0;                 // bottom row (a10,a11)

#pragma unroll
    for (int ki = 0; ki < 5; ki++)
#pragma unroll
        for (int kj = 0; kj < 5; kj++) {
            float w = sw[ki*5 + kj];
            u64 ww = pk2(w, w);
            u64 aT = pk2(in[ki  ][kj], in[ki  ][kj+1]);
            u64 aB = pk2(in[ki+1][kj], in[ki+1][kj+1]);
            {
                u64 p  = mul2(aT, ww);
                u64 e  = fma2(aT, ww, p ^ SGN);
                FeT = add2(FeT, e);
                u64 t1 = add2(p, M18);
                u64 hf = add2(t1, nM18);
                AhT = add2(AhT, hf);
                u64 r1 = fma2(hf, NEG1, p);
                ArT = add2(ArT, r1);
            }
            {
                u64 p  = mul2(aB, ww);
                u64 e  = fma2(aB, ww, p ^ SGN);
                FeB = add2(FeB, e);
                u64 t1 = add2(p, M18);
                u64 hf = add2(t1, nM18);
                AhB = add2(AhB, hf);
                u64 r1 = fma2(hf, NEG1, p);
                ArB = add2(ArB, r1);
            }
        }

    float bias = __ldg(&b1[cch]);
    float ah0, ah1, ar0, ar1, fe0, fe1;
    float s00, s01, s10, s11;

    upk2(AhT, ah0, ah1); upk2(ArT, ar0, ar1); upk2(FeT, fe0, fe1);
    s00 = __fadd_rn(__fadd_rn(ah0, __fadd_rn(ar0, fe0)), bias);
    s01 = __fadd_rn(__fadd_rn(ah1, __fadd_rn(ar1, fe1)), bias);
    upk2(AhB, ah0, ah1); upk2(ArB, ar0, ar1); upk2(FeB, fe0, fe1);
    s10 = __fadd_rn(__fadd_rn(ah0, __fadd_rn(ar0, fe0)), bias);
    s11 = __fadd_rn(__fadd_rn(ah1, __fadd_rn(ar1, fe1)), bias);

    float* outp = g_c1 + ((size_t)tb*20 + cch)*576;
    *(float2*)&outp[(y0  )*24 + x0] = make_float2(s00, s01);
    *(float2*)&outp[(y0+1)*24 + x0] = make_float2(s10, s11);
}

// ---------------- K2: ALL 64 timesteps, persistent (samples independent) ----
// grid 128, block 1024 = two independent 512-thread halves (one sample each).
// Halves synchronize via NAMED barriers so their phases don't couple.
__global__ __launch_bounds__(1024) void k_steps(
    const float* __restrict__ b2, const float* __restrict__ b_fc,
    float* __restrict__ volt)
{
    __shared__ float s_in[2][2880];
    __shared__ int   s_off[512];
    __shared__ float s_sp1[2][800];
    __shared__ float s_z2[2][512];

    int half = threadIdx.x >> 9;
    int tid  = threadIdx.x & 511;
    int b    = blockIdx.x*2 + half;
    int lane = tid & 31;
    int warp = tid >> 5;              // 0..15 within half
    int barid = 1 + half;

    if (threadIdx.x < 512) {
        int tt = (threadIdx.x < 500) ? (int)threadIdx.x : 0;
        int ci = tt / 25, k = tt % 25;
        s_off[threadIdx.x] = ci*144 + (k/5)*12 + (k%5);
    }

    int yp = warp >> 2, xq = warp & 3;
    int co = lane, co2 = lane + 32;
    float bias0 = __ldg(&b2[co]);
    float bias1 = (co2 < 50) ? __ldg(&b2[co2]) : 0.f;
    float biasf = (tid < 500) ? __ldg(&b_fc[tid]) : 0.f;
    float* v0p = g_v0 + b*11520;
    float* i0p = g_i0 + b*11520;

    __syncthreads();                  // s_off visible to both halves

    for (int t = 0; t < TSTEPS; t++) {
        // ---- Phase A: LIF0 + pool ----
        {
            const float* c1 = g_c1 + ((size_t)t*BATCH + b)*11520;
            for (int q = tid; q < 2880; q += 512) {
                int c = q / 144, rr = q % 144;
                int r = rr / 12, xx = rr % 12;
                int base = (c*24 + 2*r)*24 + 2*xx;
                float zmax = 0.f;
#pragma unroll
                for (int dy = 0; dy < 2; dy++) {
                    int idx = base + dy*24;
                    float2 inp = *(const float2*)&c1[idx];
                    float2 v  = *(float2*)&v0p[idx];
                    float2 ii = *(float2*)&i0p[idx];
                    float z0, z1;
                    lif_update(v.x, ii.x, inp.x, z0);
                    lif_update(v.y, ii.y, inp.y, z1);
                    *(float2*)&v0p[idx] = v;
                    *(float2*)&i0p[idx] = ii;
                    zmax = fmaxf(zmax, fmaxf(z0, z1));
                }
                s_in[half][q] = zmax;
            }
        }
        asm volatile("bar.sync %0, 512;" :: "r"(barid) : "memory");

        // ---- Phase B: conv2 + LIF1 + pool ----
        {
            float z0max = 0.f, z1max = 0.f;
#pragma unroll
            for (int sp = 0; sp < 4; sp++) {
                int dy = sp >> 1, dx = sp & 1;
                int y = 2*yp + dy, x = 2*xq + dx;
                int base = y*12 + x;

                long long acc0 = 0, acc1 = 0;
#pragma unroll 1
                for (int ch = 0; ch < 16; ch++) {
                    float a = s_in[half][s_off[ch*32 + lane] + base];
                    unsigned m = __ballot_sync(0xffffffffu, a != 0.f);
                    if (ch == 15) m &= 0xFFFFFu;
                    while (m) {
                        int bit = __ffs(m) - 1;
                        m &= m - 1;
                        const long long* wp = g_w2ll + (ch*32 + bit)*64;
                        acc0 += __ldg(wp + lane);
                        acc1 += __ldg(wp + lane + 32);
                    }
                }
                float inp0 = __fmul_rn(10.0f, __fadd_rn(fx2f(acc0), bias0));
                float inp1 = __fmul_rn(10.0f, __fadd_rn(fx2f(acc1), bias1));

                int sidx = (b*64 + y*8 + x)*64 + lane;
                float v0 = g_v1[sidx],      i0 = g_i1[sidx];
                float v1 = g_v1[sidx + 32], i1 = g_i1[sidx + 32];
                float z0, z1;
                lif_update(v0, i0, inp0, z0);
                lif_update(v1, i1, inp1, z1);
                g_v1[sidx] = v0;      g_i1[sidx] = i0;
                g_v1[sidx + 32] = v1; g_i1[sidx + 32] = i1;
                z0max = fmaxf(z0max, z0);
                z1max = fmaxf(z1max, z1);
            }
            int pos = yp*4 + xq;
            s_sp1[half][co*16 + pos] = z0max;
            if (co2 < 50) s_sp1[half][co2*16 + pos] = z1max;
        }
        asm volatile("bar.sync %0, 512;" :: "r"(barid) : "memory");

        // ---- Phase C: FC + LIF2 ----
        {
            int m = tid;
            long long acc = 0;
#pragma unroll 1
            for (int ch = 0; ch < 25; ch++) {
                float a = s_sp1[half][ch*32 + lane];
                unsigned msk = __ballot_sync(0xffffffffu, a != 0.f);
                while (msk) {
                    int bit = __ffs(msk) - 1;
                    msk &= msk - 1;
                    acc += __ldg(&g_wfcll[(ch*32 + bit)*512 + m]);
                }
            }
            float inp = __fadd_rn(fx2f(acc), biasf);

            int sidx = b*512 + m;
            float v = g_v2[sidx], ii = g_i2[sidx];
            float z;
            lif_update(v, ii, inp, z);
            g_v2[sidx] = v;
            g_i2[sidx] = ii;
            s_z2[half][m] = (m < 500) ? z : 0.f;
        }
        asm volatile("bar.sync %0, 512;" :: "r"(barid) : "memory");

        // ---- Phase D: readout + LI ----
        if (warp < 10) {
            long long ao = 0;
            const long long* wr = g_woutll + warp*500;
#pragma unroll 1
            for (int j = lane; j < 500; j += 32)
                if (s_z2[half][j] != 0.f) ao += __ldg(wr + j);
#pragma unroll
            for (int off = 16; off; off >>= 1)
                ao += __shfl_xor_sync(0xffffffffu, ao, off);
            if (lane == 0) {
                float sum = fx2f(ao);
                int idx = b*10 + warp;
                float vo = g_vo[idx], io = g_io[idx];
                float vn = __fadd_rn(vo, __fmul_rn(LIF_BETA, __fsub_rn(io, vo)));
                g_vo[idx] = vn;
                g_io[idx] = __fadd_rn(__fmul_rn(LIF_IDEC, io), sum);
                volt[((size_t)t * BATCH + b)*10 + warp] = vn;
            }
        }
        asm volatile("bar.sync %0, 512;" :: "r"(barid) : "memory");
    }
}

// ---------------- launch -----------------------------------------------------
extern "C" void kernel_launch(void* const* d_in, const int* in_sizes, int n_in,
                              void* d_out, int out_size)
{
    const float* x     = (const float*)d_in[0];
    const float* w1    = (const float*)d_in[1];
    const float* b1    = (const float*)d_in[2];
    const float* w2    = (const float*)d_in[3];
    const float* b2    = (const float*)d_in[4];
    const float* w_fc  = (const float*)d_in[5];
    const float* b_fc  = (const float*)d_in[6];
    const float* w_out = (const float*)d_in[7];
    float* volt = (float*)d_out;

    zero_states<<<(BATCH*20*576 + 255)/256, 256>>>();
    prep_weights<<<(800*512 + 255)/256, 256>>>(w2, w_fc, w_out);

    dim3 gc1(BATCH*TSTEPS, 20);
    k_conv1_all<<<gc1, 160>>>(x, w1, b1);

    k_steps<<<BATCH/2, 1024>>>(b2, b_fc, volt);
}

// round 11
// speedup vs baseline: 29.7382x; 1.3646x over previous
#include <cuda_runtime.h>

#define BATCH 256
#define TSTEPS 64

typedef unsigned long long u64;

// ---------------- persistent state (device globals; no allocation) ----------
__device__ float g_c1[(size_t)TSTEPS*BATCH*20*576];  // conv1+bias, all timesteps
__device__ float g_v0[BATCH*20*576];
__device__ float g_i0[BATCH*20*576];
__device__ float g_v1[BATCH*64*64];       // [b][pos(8x8)][co padded to 64]
__device__ float g_i1[BATCH*64*64];
__device__ float g_v2[BATCH*512];         // [b][m padded to 512]
__device__ float g_i2[BATCH*512];
__device__ float g_vo[BATCH*10];
__device__ float g_io[BATCH*10];
__device__ long long g_w2ll[512*64];      // conv2 w * 2^52, [t pad 512][co pad 64]
__device__ long long g_wfcll[800*512];    // fc w * 2^52, [k][m pad 512]
__device__ long long g_woutll[10*500];    // w_out * 2^52
// nibble-sum tables (exact int64 partial sums of 4-term groups)
__device__ long long g_tb2[128*16*64];    // [g][idx][lane*2+bank]; 1 MB
__device__ long long g_tbf[200*16*512];   // [gg][idx][m]; 13.1 MB

#define LIF_BETA 0.1f
#define LIF_IDEC 0.8f
#define LIF_VTH  1.0f

#define SCALE52_F 4503599627370496.0f     // 2^52
#define INV52_D   2.220446049250313e-16   // 2^-52

// ---------------- packed f32x2 helpers (each = two independent IEEE f32 ops) -
__device__ __forceinline__ u64 pk2(float lo, float hi) {
    u64 r; asm("mov.b64 %0, {%1, %2};" : "=l"(r) : "f"(lo), "f"(hi)); return r;
}
__device__ __forceinline__ void upk2(u64 v, float& lo, float& hi) {
    asm("mov.b64 {%0, %1}, %2;" : "=f"(lo), "=f"(hi) : "l"(v));
}
__device__ __forceinline__ u64 mul2(u64 a, u64 b) {
    u64 r; asm("mul.rn.f32x2 %0, %1, %2;" : "=l"(r) : "l"(a), "l"(b)); return r;
}
__device__ __forceinline__ u64 add2(u64 a, u64 b) {
    u64 r; asm("add.rn.f32x2 %0, %1, %2;" : "=l"(r) : "l"(a), "l"(b)); return r;
}
__device__ __forceinline__ u64 fma2(u64 a, u64 b, u64 c) {
    u64 r; asm("fma.rn.f32x2 %0, %1, %2, %3;" : "=l"(r) : "l"(a), "l"(b), "l"(c)); return r;
}

// LIF update with STRICT per-op rounding (no FMA contraction):
__device__ __forceinline__ void lif_update(float& v, float& i, float inp, float& z)
{
    float vd = __fadd_rn(v, __fmul_rn(LIF_BETA, __fsub_rn(i, v)));
    z = (vd > LIF_VTH) ? 1.f : 0.f;
    v = __fmul_rn(__fsub_rn(1.f, z), vd);
    i = __fadd_rn(__fmul_rn(LIF_IDEC, i), inp);
}

__device__ __forceinline__ float fx2f(long long acc)
{
    return (float)((double)acc * INV52_D);
}

// ---------------- setup kernels ---------------------------------------------
__global__ void zero_states() {
    int i = blockIdx.x * blockDim.x + threadIdx.x;
    if (i < BATCH*20*576) { g_v0[i] = 0.f; g_i0[i] = 0.f; }
    if (i < BATCH*64*64)  { g_v1[i] = 0.f; g_i1[i] = 0.f; }
    if (i < BATCH*512)    { g_v2[i] = 0.f; g_i2[i] = 0.f; }
    if (i < BATCH*10)     { g_vo[i] = 0.f; g_io[i] = 0.f; }
}

__global__ void prep_weights(const float* __restrict__ w2,
                             const float* __restrict__ w_fc,
                             const float* __restrict__ w_out) {
    int i = blockIdx.x * blockDim.x + threadIdx.x;
    if (i < 512*64) {                 // conv2: [t][co], t = ci*25+k
        int t = i >> 6, co = i & 63;
        float w = (t < 500 && co < 50) ? w2[co*500 + t] : 0.f;
        g_w2ll[i] = __float2ll_rn(__fmul_rn(w, SCALE52_F));
    }
    if (i < 800*512) {                // fc transpose: [k][m]
        int k = i >> 9, m = i & 511;
        float w = (m < 500) ? w_fc[m*800 + k] : 0.f;
        g_wfcll[i] = __float2ll_rn(__fmul_rn(w, SCALE52_F));
    }
    if (i < 10*500) {
        g_woutll[i] = __float2ll_rn(__fmul_rn(w_out[i], SCALE52_F));
    }
}

// Build nibble-sum tables from the exact int64 weights. Integer addition is
// associative -> conv2/FC sums computed via these tables are BIT-IDENTICAL
// to per-term accumulation.
__global__ void prep_tables() {
    int i = blockIdx.x * blockDim.x + threadIdx.x;
    if (i < 128*16*64) {              // conv2: f = (g*16+idx)*64 + lane*2 + bank
        int bank = i & 1, lane = (i >> 1) & 31, idx = (i >> 6) & 15, g = i >> 10;
        int co = lane + bank*32;
        long long s = 0;
#pragma unroll
        for (int j = 0; j < 4; j++)
            if ((idx >> j) & 1) s += g_w2ll[(4*g + j)*64 + co];
        g_tb2[i] = s;
    }
    if (i < 200*16*512) {             // fc: f = (gg*16+idx)*512 + m
        int m = i & 511, idx = (i >> 9) & 15, gg = i >> 13;
        long long s = 0;
#pragma unroll
        for (int j = 0; j < 4; j++)
            if ((idx >> j) & 1) s += g_wfcll[(4*gg + j)*512 + m];
        g_tbf[i] = s;
    }
}

// ---------------- K1: conv1 for ALL timesteps (state-independent) -----------
// grid (B*T, 20), block 160. Thread = one pooled quad; packed f32x2 limb
// accumulation (near-exact, deviation ~1e-12 from exact real sum).
__global__ __launch_bounds__(160) void k_conv1_all(
    const float* __restrict__ x, const float* __restrict__ w1,
    const float* __restrict__ b1)
{
    __shared__ float sx[784];
    __shared__ float sw[25];
    int tb = blockIdx.x;              // t*BATCH + b
    int cch = blockIdx.y;
    int tid = threadIdx.x;
    const float* xp = x + (size_t)tb * 784;
    for (int i = tid; i < 784; i += 160) sx[i] = xp[i];
    if (tid < 25) sw[tid] = w1[cch*25 + tid];
    __syncthreads();
    if (tid >= 144) return;

    int yp = tid / 12, xq = tid % 12;
    int y0 = 2*yp, x0 = 2*xq;

    float in[6][6];
#pragma unroll
    for (int i = 0; i < 6; i++)
#pragma unroll
        for (int j = 0; j < 6; j++)
            in[i][j] = sx[(y0+i)*28 + x0 + j];

    const u64 SGN  = 0x8000000080000000ULL;
    const u64 M18  = pk2(48.0f, 48.0f);            // 1.5*2^5 -> grid 2^-18
    const u64 nM18 = pk2(-48.0f, -48.0f);
    const u64 NEG1 = pk2(-1.0f, -1.0f);

    u64 AhT = 0, ArT = 0, FeT = 0;                 // top row (a00,a01)
    u64 AhB = 0, ArB = 0, FeB = 0;                 // bottom row (a10,a11)

#pragma unroll
    for (int ki = 0; ki < 5; ki++)
#pragma unroll
        for (int kj = 0; kj < 5; kj++) {
            float w = sw[ki*5 + kj];
            u64 ww = pk2(w, w);
            u64 aT = pk2(in[ki  ][kj], in[ki  ][kj+1]);
            u64 aB = pk2(in[ki+1][kj], in[ki+1][kj+1]);
            {
                u64 p  = mul2(aT, ww);
                u64 e  = fma2(aT, ww, p ^ SGN);
                FeT = add2(FeT, e);
                u64 t1 = add2(p, M18);
                u64 hf = add2(t1, nM18);
                AhT = add2(AhT, hf);
                u64 r1 = fma2(hf, NEG1, p);
                ArT = add2(ArT, r1);
            }
            {
                u64 p  = mul2(aB, ww);
                u64 e  = fma2(aB, ww, p ^ SGN);
                FeB = add2(FeB, e);
                u64 t1 = add2(p, M18);
                u64 hf = add2(t1, nM18);
                AhB = add2(AhB, hf);
                u64 r1 = fma2(hf, NEG1, p);
                ArB = add2(ArB, r1);
            }
        }

    float bias = __ldg(&b1[cch]);
    float ah0, ah1, ar0, ar1, fe0, fe1;
    float s00, s01, s10, s11;

    upk2(AhT, ah0, ah1); upk2(ArT, ar0, ar1); upk2(FeT, fe0, fe1);
    s00 = __fadd_rn(__fadd_rn(ah0, __fadd_rn(ar0, fe0)), bias);
    s01 = __fadd_rn(__fadd_rn(ah1, __fadd_rn(ar1, fe1)), bias);
    upk2(AhB, ah0, ah1); upk2(ArB, ar0, ar1); upk2(FeB, fe0, fe1);
    s10 = __fadd_rn(__fadd_rn(ah0, __fadd_rn(ar0, fe0)), bias);
    s11 = __fadd_rn(__fadd_rn(ah1, __fadd_rn(ar1, fe1)), bias);

    float* outp = g_c1 + ((size_t)tb*20 + cch)*576;
    *(float2*)&outp[(y0  )*24 + x0] = make_float2(s00, s01);
    *(float2*)&outp[(y0+1)*24 + x0] = make_float2(s10, s11);
}

// ---------------- K2: ALL 64 timesteps, persistent (samples independent) ----
// grid 128, block 1024 = two independent 512-thread halves (one sample each),
// synced by named barriers. Conv2/FC use nibble-sum tables: 4 terms per load.
__global__ __launch_bounds__(1024) void k_steps(
    const float* __restrict__ b2, const float* __restrict__ b_fc,
    float* __restrict__ volt)
{
    __shared__ float s_in[2][2880];
    __shared__ int   s_off[512];
    __shared__ float s_sp1[2][800];
    __shared__ float s_z2[2][512];

    int half = threadIdx.x >> 9;
    int tid  = threadIdx.x & 511;
    int b    = blockIdx.x*2 + half;
    int lane = tid & 31;
    int warp = tid >> 5;              // 0..15 within half
    int barid = 1 + half;

    if (threadIdx.x < 512) {
        int tt = (threadIdx.x < 500) ? (int)threadIdx.x : 0;
        int ci = tt / 25, k = tt % 25;
        s_off[threadIdx.x] = ci*144 + (k/5)*12 + (k%5);
    }

    int yp = warp >> 2, xq = warp & 3;
    int co = lane, co2 = lane + 32;
    float bias0 = __ldg(&b2[co]);
    float bias1 = (co2 < 50) ? __ldg(&b2[co2]) : 0.f;
    float biasf = (tid < 500) ? __ldg(&b_fc[tid]) : 0.f;
    float* v0p = g_v0 + b*11520;
    float* i0p = g_i0 + b*11520;

    __syncthreads();                  // s_off visible to both halves

    for (int t = 0; t < TSTEPS; t++) {
        // ---- Phase A: LIF0 + pool ----
        {
            const float* c1 = g_c1 + ((size_t)t*BATCH + b)*11520;
            for (int q = tid; q < 2880; q += 512) {
                int c = q / 144, rr = q % 144;
                int r = rr / 12, xx = rr % 12;
                int base = (c*24 + 2*r)*24 + 2*xx;
                float zmax = 0.f;
#pragma unroll
                for (int dy = 0; dy < 2; dy++) {
                    int idx = base + dy*24;
                    float2 inp = *(const float2*)&c1[idx];
                    float2 v  = *(float2*)&v0p[idx];
                    float2 ii = *(float2*)&i0p[idx];
                    float z0, z1;
                    lif_update(v.x, ii.x, inp.x, z0);
                    lif_update(v.y, ii.y, inp.y, z1);
                    *(float2*)&v0p[idx] = v;
                    *(float2*)&i0p[idx] = ii;
                    zmax = fmaxf(zmax, fmaxf(z0, z1));
                }
                s_in[half][q] = zmax;
            }
        }
        asm volatile("bar.sync %0, 512;" :: "r"(barid) : "memory");

        // ---- Phase B: conv2 + LIF1 + pool (nibble tables) ----
        // Ballot bits >= term 500 (chunk 15, lanes 20-31) index groups 125-127
        // whose table entries are exact zero (zero-padded weights) -> harmless.
        {
            float z0max = 0.f, z1max = 0.f;
#pragma unroll
            for (int sp = 0; sp < 4; sp++) {
                int dy = sp >> 1, dx = sp & 1;
                int y = 2*yp + dy, x = 2*xq + dx;
                int base = y*12 + x;

                long long acc0 = 0, acc1 = 0;
#pragma unroll 1
                for (int ch = 0; ch < 16; ch++) {
                    float a = s_in[half][s_off[ch*32 + lane] + base];
                    unsigned msk = __ballot_sync(0xffffffffu, a != 0.f);
#pragma unroll
                    for (int j = 0; j < 8; j++) {
                        unsigned idx = (msk >> (4*j)) & 15u;
                        if (idx) {
                            const longlong2 wv = *(const longlong2*)
                                &g_tb2[((ch*8 + j)*16 + idx)*64 + lane*2];
                            acc0 += wv.x;
                            acc1 += wv.y;
                        }
                    }
                }
                float inp0 = __fmul_rn(10.0f, __fadd_rn(fx2f(acc0), bias0));
                float inp1 = __fmul_rn(10.0f, __fadd_rn(fx2f(acc1), bias1));

                int sidx = (b*64 + y*8 + x)*64 + lane;
                float v0 = g_v1[sidx],      i0 = g_i1[sidx];
                float v1 = g_v1[sidx + 32], i1 = g_i1[sidx + 32];
                float z0, z1;
                lif_update(v0, i0, inp0, z0);
                lif_update(v1, i1, inp1, z1);
                g_v1[sidx] = v0;      g_i1[sidx] = i0;
                g_v1[sidx + 32] = v1; g_i1[sidx + 32] = i1;
                z0max = fmaxf(z0max, z0);
                z1max = fmaxf(z1max, z1);
            }
            int pos = yp*4 + xq;
            s_sp1[half][co*16 + pos] = z0max;
            if (co2 < 50) s_sp1[half][co2*16 + pos] = z1max;
        }
        asm volatile("bar.sync %0, 512;" :: "r"(barid) : "memory");

        // ---- Phase C: FC + LIF2 (nibble tables) ----
        {
            int m = tid;
            long long acc = 0;
#pragma unroll 1
            for (int ch = 0; ch < 25; ch++) {
                float a = s_sp1[half][ch*32 + lane];
                unsigned msk = __ballot_sync(0xffffffffu, a != 0.f);
#pragma unroll
                for (int j = 0; j < 8; j++) {
                    unsigned idx = (msk >> (4*j)) & 15u;
                    if (idx)
                        acc += __ldg(&g_tbf[((ch*8 + j)*16 + idx)*512 + m]);
                }
            }
            float inp = __fadd_rn(fx2f(acc), biasf);

            int sidx = b*512 + m;
            float v = g_v2[sidx], ii = g_i2[sidx];
            float z;
            lif_update(v, ii, inp, z);
            g_v2[sidx] = v;
            g_i2[sidx] = ii;
            s_z2[half][m] = (m < 500) ? z : 0.f;
        }
        asm volatile("bar.sync %0, 512;" :: "r"(barid) : "memory");

        // ---- Phase D: readout + LI ----
        if (warp < 10) {
            long long ao = 0;
            const long long* wr = g_woutll + warp*500;
#pragma unroll 1
            for (int j = lane; j < 500; j += 32)
                if (s_z2[half][j] != 0.f) ao += __ldg(wr + j);
#pragma unroll
            for (int off = 16; off; off >>= 1)
                ao += __shfl_xor_sync(0xffffffffu, ao, off);
            if (lane == 0) {
                float sum = fx2f(ao);
                int idx = b*10 + warp;
                float vo = g_vo[idx], io = g_io[idx];
                float vn = __fadd_rn(vo, __fmul_rn(LIF_BETA, __fsub_rn(io, vo)));
                g_vo[idx] = vn;
                g_io[idx] = __fadd_rn(__fmul_rn(LIF_IDEC, io), sum);
                volt[((size_t)t * BATCH + b)*10 + warp] = vn;
            }
        }
        asm volatile("bar.sync %0, 512;" :: "r"(barid) : "memory");
    }
}

// ---------------- launch -----------------------------------------------------
extern "C" void kernel_launch(void* const* d_in, const int* in_sizes, int n_in,
                              void* d_out, int out_size)
{
    const float* x     = (const float*)d_in[0];
    const float* w1    = (const float*)d_in[1];
    const float* b1    = (const float*)d_in[2];
    const float* w2    = (const float*)d_in[3];
    const float* b2    = (const float*)d_in[4];
    const float* w_fc  = (const float*)d_in[5];
    const float* b_fc  = (const float*)d_in[6];
    const float* w_out = (const float*)d_in[7];
    float* volt = (float*)d_out;

    zero_states<<<(BATCH*20*576 + 255)/256, 256>>>();
    prep_weights<<<(800*512 + 255)/256, 256>>>(w2, w_fc, w_out);
    prep_tables<<<(200*16*512 + 255)/256, 256>>>();

    dim3 gc1(BATCH*TSTEPS, 20);
    k_conv1_all<<<gc1, 160>>>(x, w1, b1);

    k_steps<<<BATCH/2, 1024>>>(b2, b_fc, volt);
}

// round 12
// speedup vs baseline: 36.5205x; 1.2281x over previous
#include <cuda_runtime.h>

#define BATCH 256
#define TSTEPS 64

typedef unsigned long long u64;

// ---------------- persistent state (device globals; no allocation) ----------
__device__ float g_c1[(size_t)TSTEPS*BATCH*20*576];  // conv1+bias, all timesteps
__device__ float g_v0[BATCH*20*576];
__device__ float g_i0[BATCH*20*576];
__device__ float g_v1[BATCH*64*64];       // [b][pos(8x8)][co padded to 64]
__device__ float g_i1[BATCH*64*64];
__device__ float g_v2[BATCH*512];         // [b][m padded to 512]
__device__ float g_i2[BATCH*512];
__device__ float g_vo[BATCH*10];
__device__ float g_io[BATCH*10];
__device__ long long g_w2ll[512*64];      // conv2 w * 2^52, [t pad 512][co pad 64]
__device__ long long g_wfcll[800*512];    // fc w * 2^52, [k][m pad 512]
__device__ long long g_woutll[10*500];    // w_out * 2^52
// exact int64 partial-sum tables
__device__ long long g_tb2b[64*256*64];   // conv2 BYTE table: [g][idx][lane*2+bank]; 8.4 MB
__device__ long long g_tbf[200*16*512];   // fc NIBBLE table: [gg][idx][m]; 13.1 MB

#define LIF_BETA 0.1f
#define LIF_IDEC 0.8f
#define LIF_VTH  1.0f

#define SCALE52_F 4503599627370496.0f     // 2^52
#define INV52_D   2.220446049250313e-16   // 2^-52

// ---------------- packed f32x2 helpers (each = two independent IEEE f32 ops) -
__device__ __forceinline__ u64 pk2(float lo, float hi) {
    u64 r; asm("mov.b64 %0, {%1, %2};" : "=l"(r) : "f"(lo), "f"(hi)); return r;
}
__device__ __forceinline__ void upk2(u64 v, float& lo, float& hi) {
    asm("mov.b64 {%0, %1}, %2;" : "=f"(lo), "=f"(hi) : "l"(v));
}
__device__ __forceinline__ u64 mul2(u64 a, u64 b) {
    u64 r; asm("mul.rn.f32x2 %0, %1, %2;" : "=l"(r) : "l"(a), "l"(b)); return r;
}
__device__ __forceinline__ u64 add2(u64 a, u64 b) {
    u64 r; asm("add.rn.f32x2 %0, %1, %2;" : "=l"(r) : "l"(a), "l"(b)); return r;
}
__device__ __forceinline__ u64 fma2(u64 a, u64 b, u64 c) {
    u64 r; asm("fma.rn.f32x2 %0, %1, %2, %3;" : "=l"(r) : "l"(a), "l"(b), "l"(c)); return r;
}

// LIF update with STRICT per-op rounding (no FMA contraction):
__device__ __forceinline__ void lif_update(float& v, float& i, float inp, float& z)
{
    float vd = __fadd_rn(v, __fmul_rn(LIF_BETA, __fsub_rn(i, v)));
    z = (vd > LIF_VTH) ? 1.f : 0.f;
    v = __fmul_rn(__fsub_rn(1.f, z), vd);
    i = __fadd_rn(__fmul_rn(LIF_IDEC, i), inp);
}

__device__ __forceinline__ float fx2f(long long acc)
{
    return (float)((double)acc * INV52_D);
}

// ---------------- setup kernels ---------------------------------------------
__global__ void zero_states() {
    int i = blockIdx.x * blockDim.x + threadIdx.x;
    if (i < BATCH*20*576) { g_v0[i] = 0.f; g_i0[i] = 0.f; }
    if (i < BATCH*64*64)  { g_v1[i] = 0.f; g_i1[i] = 0.f; }
    if (i < BATCH*512)    { g_v2[i] = 0.f; g_i2[i] = 0.f; }
    if (i < BATCH*10)     { g_vo[i] = 0.f; g_io[i] = 0.f; }
}

__global__ void prep_weights(const float* __restrict__ w2,
                             const float* __restrict__ w_fc,
                             const float* __restrict__ w_out) {
    int i = blockIdx.x * blockDim.x + threadIdx.x;
    if (i < 512*64) {                 // conv2: [t][co], t = ci*25+k
        int t = i >> 6, co = i & 63;
        float w = (t < 500 && co < 50) ? w2[co*500 + t] : 0.f;
        g_w2ll[i] = __float2ll_rn(__fmul_rn(w, SCALE52_F));
    }
    if (i < 800*512) {                // fc transpose: [k][m]
        int k = i >> 9, m = i & 511;
        float w = (m < 500) ? w_fc[m*800 + k] : 0.f;
        g_wfcll[i] = __float2ll_rn(__fmul_rn(w, SCALE52_F));
    }
    if (i < 10*500) {
        g_woutll[i] = __float2ll_rn(__fmul_rn(w_out[i], SCALE52_F));
    }
}

// Build partial-sum tables from the exact int64 weights. Integer addition is
// associative -> sums computed via these tables are BIT-IDENTICAL to
// per-term accumulation.
__global__ void prep_tables() {
    int i = blockIdx.x * blockDim.x + threadIdx.x;
    if (i < 64*256*64) {              // conv2 byte table
        int bank = i & 1, lane = (i >> 1) & 31;
        int idx = (i >> 6) & 255, g = i >> 14;
        int co = lane + bank*32;
        long long s = 0;
#pragma unroll
        for (int j = 0; j < 8; j++)
            if ((idx >> j) & 1) s += g_w2ll[(8*g + j)*64 + co];
        g_tb2b[i] = s;
    }
    if (i < 200*16*512) {             // fc nibble table
        int m = i & 511, idx = (i >> 9) & 15, gg = i >> 13;
        long long s = 0;
#pragma unroll
        for (int j = 0; j < 4; j++)
            if ((idx >> j) & 1) s += g_wfcll[(4*gg + j)*512 + m];
        g_tbf[i] = s;
    }
}

// ---------------- K1: conv1 for ALL timesteps (state-independent) -----------
// grid (B*T, 20), block 160. Thread = one pooled quad; packed f32x2 limb
// accumulation (near-exact, deviation ~1e-12 from exact real sum).
__global__ __launch_bounds__(160) void k_conv1_all(
    const float* __restrict__ x, const float* __restrict__ w1,
    const float* __restrict__ b1)
{
    __shared__ float sx[784];
    __shared__ float sw[25];
    int tb = blockIdx.x;              // t*BATCH + b
    int cch = blockIdx.y;
    int tid = threadIdx.x;
    const float* xp = x + (size_t)tb * 784;
    for (int i = tid; i < 784; i += 160) sx[i] = xp[i];
    if (tid < 25) sw[tid] = w1[cch*25 + tid];
    __syncthreads();
    if (tid >= 144) return;

    int yp = tid / 12, xq = tid % 12;
    int y0 = 2*yp, x0 = 2*xq;

    float in[6][6];
#pragma unroll
    for (int i = 0; i < 6; i++)
#pragma unroll
        for (int j = 0; j < 6; j++)
            in[i][j] = sx[(y0+i)*28 + x0 + j];

    const u64 SGN  = 0x8000000080000000ULL;
    const u64 M18  = pk2(48.0f, 48.0f);            // 1.5*2^5 -> grid 2^-18
    const u64 nM18 = pk2(-48.0f, -48.0f);
    const u64 NEG1 = pk2(-1.0f, -1.0f);

    u64 AhT = 0, ArT = 0, FeT = 0;                 // top row (a00,a01)
    u64 AhB = 0, ArB = 0, FeB = 0;                 // bottom row (a10,a11)

#pragma unroll
    for (int ki = 0; ki < 5; ki++)
#pragma unroll
        for (int kj = 0; kj < 5; kj++) {
            float w = sw[ki*5 + kj];
            u64 ww = pk2(w, w);
            u64 aT = pk2(in[ki  ][kj], in[ki  ][kj+1]);
            u64 aB = pk2(in[ki+1][kj], in[ki+1][kj+1]);
            {
                u64 p  = mul2(aT, ww);
                u64 e  = fma2(aT, ww, p ^ SGN);
                FeT = add2(FeT, e);
                u64 t1 = add2(p, M18);
                u64 hf = add2(t1, nM18);
                AhT = add2(AhT, hf);
                u64 r1 = fma2(hf, NEG1, p);
                ArT = add2(ArT, r1);
            }
            {
                u64 p  = mul2(aB, ww);
                u64 e  = fma2(aB, ww, p ^ SGN);
                FeB = add2(FeB, e);
                u64 t1 = add2(p, M18);
                u64 hf = add2(t1, nM18);
                AhB = add2(AhB, hf);
                u64 r1 = fma2(hf, NEG1, p);
                ArB = add2(ArB, r1);
            }
        }

    float bias = __ldg(&b1[cch]);
    float ah0, ah1, ar0, ar1, fe0, fe1;
    float s00, s01, s10, s11;

    upk2(AhT, ah0, ah1); upk2(ArT, ar0, ar1); upk2(FeT, fe0, fe1);
    s00 = __fadd_rn(__fadd_rn(ah0, __fadd_rn(ar0, fe0)), bias);
    s01 = __fadd_rn(__fadd_rn(ah1, __fadd_rn(ar1, fe1)), bias);
    upk2(AhB, ah0, ah1); upk2(ArB, ar0, ar1); upk2(FeB, fe0, fe1);
    s10 = __fadd_rn(__fadd_rn(ah0, __fadd_rn(ar0, fe0)), bias);
    s11 = __fadd_rn(__fadd_rn(ah1, __fadd_rn(ar1, fe1)), bias);

    float* outp = g_c1 + ((size_t)tb*20 + cch)*576;
    *(float2*)&outp[(y0  )*24 + x0] = make_float2(s00, s01);
    *(float2*)&outp[(y0+1)*24 + x0] = make_float2(s10, s11);
}

// ---------------- K2: ALL 64 timesteps, persistent (samples independent) ----
// grid 128, block 1024 = two independent 512-thread halves (one sample each),
// synced by named barriers. Conv2 uses BYTE tables (8 terms/load); FC nibble.
__global__ __launch_bounds__(1024) void k_steps(
    const float* __restrict__ b2, const float* __restrict__ b_fc,
    float* __restrict__ volt)
{
    __shared__ float s_in[2][2880];
    __shared__ int   s_off[512];
    __shared__ float s_sp1[2][800];
    __shared__ float s_z2[2][512];

    int half = threadIdx.x >> 9;
    int tid  = threadIdx.x & 511;
    int b    = blockIdx.x*2 + half;
    int lane = tid & 31;
    int warp = tid >> 5;              // 0..15 within half
    int barid = 1 + half;

    if (threadIdx.x < 512) {
        int tt = (threadIdx.x < 500) ? (int)threadIdx.x : 0;
        int ci = tt / 25, k = tt % 25;
        s_off[threadIdx.x] = ci*144 + (k/5)*12 + (k%5);
    }

    int yp = warp >> 2, xq = warp & 3;
    int co = lane, co2 = lane + 32;
    float bias0 = __ldg(&b2[co]);
    float bias1 = (co2 < 50) ? __ldg(&b2[co2]) : 0.f;
    float biasf = (tid < 500) ? __ldg(&b_fc[tid]) : 0.f;
    float* v0p = g_v0 + b*11520;
    float* i0p = g_i0 + b*11520;

    __syncthreads();                  // s_off visible to both halves

    for (int t = 0; t < TSTEPS; t++) {
        // ---- Phase A: LIF0 + pool ----
        {
            const float* c1 = g_c1 + ((size_t)t*BATCH + b)*11520;
            for (int q = tid; q < 2880; q += 512) {
                int c = q / 144, rr = q % 144;
                int r = rr / 12, xx = rr % 12;
                int base = (c*24 + 2*r)*24 + 2*xx;
                float zmax = 0.f;
#pragma unroll
                for (int dy = 0; dy < 2; dy++) {
                    int idx = base + dy*24;
                    float2 inp = *(const float2*)&c1[idx];
                    float2 v  = *(float2*)&v0p[idx];
                    float2 ii = *(float2*)&i0p[idx];
                    float z0, z1;
                    lif_update(v.x, ii.x, inp.x, z0);
                    lif_update(v.y, ii.y, inp.y, z1);
                    *(float2*)&v0p[idx] = v;
                    *(float2*)&i0p[idx] = ii;
                    zmax = fmaxf(zmax, fmaxf(z0, z1));
                }
                s_in[half][q] = zmax;
            }
        }
        asm volatile("bar.sync %0, 512;" :: "r"(barid) : "memory");

        // ---- Phase B: conv2 + LIF1 + pool (byte tables, 8 terms/load) ----
        // Ballot bits >= term 500 index byte-groups built from zero-padded
        // weight rows -> contribute exact 0; no masking needed.
        {
            float z0max = 0.f, z1max = 0.f;
#pragma unroll
            for (int sp = 0; sp < 4; sp++) {
                int dy = sp >> 1, dx = sp & 1;
                int y = 2*yp + dy, x = 2*xq + dx;
                int base = y*12 + x;

                long long acc0 = 0, acc1 = 0;
#pragma unroll 1
                for (int ch = 0; ch < 16; ch++) {
                    float a = s_in[half][s_off[ch*32 + lane] + base];
                    unsigned msk = __ballot_sync(0xffffffffu, a != 0.f);
#pragma unroll
                    for (int j = 0; j < 4; j++) {
                        unsigned idx = (msk >> (8*j)) & 255u;
                        if (idx) {
                            const longlong2 wv = *(const longlong2*)
                                &g_tb2b[((ch*4 + j)*256 + idx)*64 + lane*2];
                            acc0 += wv.x;
                            acc1 += wv.y;
                        }
                    }
                }
                float inp0 = __fmul_rn(10.0f, __fadd_rn(fx2f(acc0), bias0));
                float inp1 = __fmul_rn(10.0f, __fadd_rn(fx2f(acc1), bias1));

                int sidx = (b*64 + y*8 + x)*64 + lane;
                float v0 = g_v1[sidx],      i0 = g_i1[sidx];
                float v1 = g_v1[sidx + 32], i1 = g_i1[sidx + 32];
                float z0, z1;
                lif_update(v0, i0, inp0, z0);
                lif_update(v1, i1, inp1, z1);
                g_v1[sidx] = v0;      g_i1[sidx] = i0;
                g_v1[sidx + 32] = v1; g_i1[sidx + 32] = i1;
                z0max = fmaxf(z0max, z0);
                z1max = fmaxf(z1max, z1);
            }
            int pos = yp*4 + xq;
            s_sp1[half][co*16 + pos] = z0max;
            if (co2 < 50) s_sp1[half][co2*16 + pos] = z1max;
        }
        asm volatile("bar.sync %0, 512;" :: "r"(barid) : "memory");

        // ---- Phase C: FC + LIF2 (nibble tables) ----
        {
            int m = tid;
            long long acc = 0;
#pragma unroll 1
            for (int ch = 0; ch < 25; ch++) {
                float a = s_sp1[half][ch*32 + lane];
                unsigned msk = __ballot_sync(0xffffffffu, a != 0.f);
#pragma unroll
                for (int j = 0; j < 8; j++) {
                    unsigned idx = (msk >> (4*j)) & 15u;
                    if (idx)
                        acc += __ldg(&g_tbf[((ch*8 + j)*16 + idx)*512 + m]);
                }
            }
            float inp = __fadd_rn(fx2f(acc), biasf);

            int sidx = b*512 + m;
            float v = g_v2[sidx], ii = g_i2[sidx];
            float z;
            lif_update(v, ii, inp, z);
            g_v2[sidx] = v;
            g_i2[sidx] = ii;
            s_z2[half][m] = (m < 500) ? z : 0.f;
        }
        asm volatile("bar.sync %0, 512;" :: "r"(barid) : "memory");

        // ---- Phase D: readout + LI ----
        if (warp < 10) {
            long long ao = 0;
            const long long* wr = g_woutll + warp*500;
#pragma unroll 1
            for (int j = lane; j < 500; j += 32)
                if (s_z2[half][j] != 0.f) ao += __ldg(wr + j);
#pragma unroll
            for (int off = 16; off; off >>= 1)
                ao += __shfl_xor_sync(0xffffffffu, ao, off);
            if (lane == 0) {
                float sum = fx2f(ao);
                int idx = b*10 + warp;
                float vo = g_vo[idx], io = g_io[idx];
                float vn = __fadd_rn(vo, __fmul_rn(LIF_BETA, __fsub_rn(io, vo)));
                g_vo[idx] = vn;
                g_io[idx] = __fadd_rn(__fmul_rn(LIF_IDEC, io), sum);
                volt[((size_t)t * BATCH + b)*10 + warp] = vn;
            }
        }
        asm volatile("bar.sync %0, 512;" :: "r"(barid) : "memory");
    }
}

// ---------------- launch -----------------------------------------------------
extern "C" void kernel_launch(void* const* d_in, const int* in_sizes, int n_in,
                              void* d_out, int out_size)
{
    const float* x     = (const float*)d_in[0];
    const float* w1    = (const float*)d_in[1];
    const float* b1    = (const float*)d_in[2];
    const float* w2    = (const float*)d_in[3];
    const float* b2    = (const float*)d_in[4];
    const float* w_fc  = (const float*)d_in[5];
    const float* b_fc  = (const float*)d_in[6];
    const float* w_out = (const float*)d_in[7];
    float* volt = (float*)d_out;

    zero_states<<<(BATCH*20*576 + 255)/256, 256>>>();
    prep_weights<<<(800*512 + 255)/256, 256>>>(w2, w_fc, w_out);
    prep_tables<<<(200*16*512 + 255)/256, 256>>>();

    dim3 gc1(BATCH*TSTEPS, 20);
    k_conv1_all<<<gc1, 160>>>(x, w1, b1);

    k_steps<<<BATCH/2, 1024>>>(b2, b_fc, volt);
}

// round 13
// speedup vs baseline: 39.6835x; 1.0866x over previous
#include <cuda_runtime.h>

#define BATCH 256
#define TSTEPS 64

typedef unsigned long long u64;

// ---------------- persistent state (device globals; no allocation) ----------
__device__ float g_c1[(size_t)TSTEPS*BATCH*20*576];  // conv1+bias, all timesteps
__device__ float g_v0[BATCH*20*576];
__device__ float g_i0[BATCH*20*576];
__device__ float g_v1[BATCH*64*64];       // [b][pos(8x8)][co padded to 64]
__device__ float g_i1[BATCH*64*64];
__device__ float g_v2[BATCH*512];         // [b][m padded to 512]
__device__ float g_i2[BATCH*512];
__device__ float g_vo[BATCH*10];
__device__ float g_io[BATCH*10];
__device__ long long g_w2ll[512*64];      // conv2 w * 2^52, [t pad 512][co pad 64]
__device__ long long g_wfcll[800*512];    // fc w * 2^52, [k][m pad 512]
__device__ long long g_woutll[10*500];    // w_out * 2^52
// exact int64 partial-sum tables
__device__ long long g_tb2b[64*256*64];   // conv2 BYTE table: [g][idx][lane*2+bank]; 8.4 MB
__device__ long long g_tbf[200*16*512];   // fc NIBBLE table: [gg][idx][m]; 13.1 MB

#define LIF_BETA 0.1f
#define LIF_IDEC 0.8f
#define LIF_VTH  1.0f

#define SCALE52_F 4503599627370496.0f     // 2^52
#define INV52_D   2.220446049250313e-16   // 2^-52

// ---------------- packed f32x2 helpers (each = two independent IEEE f32 ops) -
__device__ __forceinline__ u64 pk2(float lo, float hi) {
    u64 r; asm("mov.b64 %0, {%1, %2};" : "=l"(r) : "f"(lo), "f"(hi)); return r;
}
__device__ __forceinline__ void upk2(u64 v, float& lo, float& hi) {
    asm("mov.b64 {%0, %1}, %2;" : "=f"(lo), "=f"(hi) : "l"(v));
}
__device__ __forceinline__ u64 add2(u64 a, u64 b) {
    u64 r; asm("add.rn.f32x2 %0, %1, %2;" : "=l"(r) : "l"(a), "l"(b)); return r;
}
__device__ __forceinline__ u64 fma2(u64 a, u64 b, u64 c) {
    u64 r; asm("fma.rn.f32x2 %0, %1, %2, %3;" : "=l"(r) : "l"(a), "l"(b), "l"(c)); return r;
}

// LIF update with STRICT per-op rounding (no FMA contraction):
__device__ __forceinline__ void lif_update(float& v, float& i, float inp, float& z)
{
    float vd = __fadd_rn(v, __fmul_rn(LIF_BETA, __fsub_rn(i, v)));
    z = (vd > LIF_VTH) ? 1.f : 0.f;
    v = __fmul_rn(__fsub_rn(1.f, z), vd);
    i = __fadd_rn(__fmul_rn(LIF_IDEC, i), inp);
}

__device__ __forceinline__ float fx2f(long long acc)
{
    return (float)((double)acc * INV52_D);
}

// ---------------- setup kernels ---------------------------------------------
__global__ void zero_states() {
    int i = blockIdx.x * blockDim.x + threadIdx.x;
    if (i < BATCH*20*576) { g_v0[i] = 0.f; g_i0[i] = 0.f; }
    if (i < BATCH*64*64)  { g_v1[i] = 0.f; g_i1[i] = 0.f; }
    if (i < BATCH*512)    { g_v2[i] = 0.f; g_i2[i] = 0.f; }
    if (i < BATCH*10)     { g_vo[i] = 0.f; g_io[i] = 0.f; }
}

__global__ void prep_weights(const float* __restrict__ w2,
                             const float* __restrict__ w_fc,
                             const float* __restrict__ w_out) {
    int i = blockIdx.x * blockDim.x + threadIdx.x;
    if (i < 512*64) {                 // conv2: [t][co], t = ci*25+k
        int t = i >> 6, co = i & 63;
        float w = (t < 500 && co < 50) ? w2[co*500 + t] : 0.f;
        g_w2ll[i] = __float2ll_rn(__fmul_rn(w, SCALE52_F));
    }
    if (i < 800*512) {                // fc transpose: [k][m]
        int k = i >> 9, m = i & 511;
        float w = (m < 500) ? w_fc[m*800 + k] : 0.f;
        g_wfcll[i] = __float2ll_rn(__fmul_rn(w, SCALE52_F));
    }
    if (i < 10*500) {
        g_woutll[i] = __float2ll_rn(__fmul_rn(w_out[i], SCALE52_F));
    }
}

// Build partial-sum tables from the exact int64 weights. Integer addition is
// associative -> sums computed via these tables are BIT-IDENTICAL to
// per-term accumulation.
__global__ void prep_tables() {
    int i = blockIdx.x * blockDim.x + threadIdx.x;
    if (i < 64*256*64) {              // conv2 byte table
        int bank = i & 1, lane = (i >> 1) & 31;
        int idx = (i >> 6) & 255, g = i >> 14;
        int co = lane + bank*32;
        long long s = 0;
#pragma unroll
        for (int j = 0; j < 8; j++)
            if ((idx >> j) & 1) s += g_w2ll[(8*g + j)*64 + co];
        g_tb2b[i] = s;
    }
    if (i < 200*16*512) {             // fc nibble table
        int m = i & 511, idx = (i >> 9) & 15, gg = i >> 13;
        long long s = 0;
#pragma unroll
        for (int j = 0; j < 4; j++)
            if ((idx >> j) & 1) s += g_wfcll[(4*gg + j)*512 + m];
        g_tbf[i] = s;
    }
}

// ---------------- K1: conv1 for ALL timesteps (state-independent) -----------
// grid (B*T, 20), block 160. Thread = one pooled quad; packed f32x2 fused limb
// accumulation: per product pair only 5 fma-pipe ops:
//   t1 = fma(a,w,MAGIC); hf = t1-MAGIC   (a*w rounded to 2^-18 grid, exact mult.)
//   Ah += hf                             (grid multiples -> exact f32 adds)
//   r  = fma(a,w,-hf)                    (remainder, repr. err <= 2^-43)
//   Fr += r                              (fp32; total rounding ~1e-11)
// Deviation from exact real sum ~1e-12 sigma -> trajectory-preserving.
__global__ __launch_bounds__(160) void k_conv1_all(
    const float* __restrict__ x, const float* __restrict__ w1,
    const float* __restrict__ b1)
{
    __shared__ float sx[784];
    __shared__ float sw[25];
    int tb = blockIdx.x;              // t*BATCH + b
    int cch = blockIdx.y;
    int tid = threadIdx.x;
    const float* xp = x + (size_t)tb * 784;
    for (int i = tid; i < 784; i += 160) sx[i] = xp[i];
    if (tid < 25) sw[tid] = w1[cch*25 + tid];
    __syncthreads();
    if (tid >= 144) return;

    int yp = tid / 12, xq = tid % 12;
    int y0 = 2*yp, x0 = 2*xq;

    float in[6][6];
#pragma unroll
    for (int i = 0; i < 6; i++)
#pragma unroll
        for (int j = 0; j < 6; j++)
            in[i][j] = sx[(y0+i)*28 + x0 + j];

    const u64 SGN  = 0x8000000080000000ULL;
    const u64 M18  = pk2(48.0f, 48.0f);            // 1.5*2^5 -> grid 2^-18
    const u64 nM18 = pk2(-48.0f, -48.0f);

    u64 AhT = 0, FrT = 0;                          // top row (a00,a01)
    u64 AhB = 0, FrB = 0;                          // bottom row (a10,a11)

#pragma unroll
    for (int ki = 0; ki < 5; ki++)
#pragma unroll
        for (int kj = 0; kj < 5; kj++) {
            float w = sw[ki*5 + kj];
            u64 ww = pk2(w, w);
            u64 aT = pk2(in[ki  ][kj], in[ki  ][kj+1]);
            u64 aB = pk2(in[ki+1][kj], in[ki+1][kj+1]);
            {
                u64 t1 = fma2(aT, ww, M18);
                u64 hf = add2(t1, nM18);
                AhT = add2(AhT, hf);
                u64 r  = fma2(aT, ww, hf ^ SGN);
                FrT = add2(FrT, r);
            }
            {
                u64 t1 = fma2(aB, ww, M18);
                u64 hf = add2(t1, nM18);
                AhB = add2(AhB, hf);
                u64 r  = fma2(aB, ww, hf ^ SGN);
                FrB = add2(FrB, r);
            }
        }

    float bias = __ldg(&b1[cch]);
    float ah0, ah1, fr0, fr1;
    float s00, s01, s10, s11;

    upk2(AhT, ah0, ah1); upk2(FrT, fr0, fr1);
    s00 = __fadd_rn(__fadd_rn(ah0, fr0), bias);
    s01 = __fadd_rn(__fadd_rn(ah1, fr1), bias);
    upk2(AhB, ah0, ah1); upk2(FrB, fr0, fr1);
    s10 = __fadd_rn(__fadd_rn(ah0, fr0), bias);
    s11 = __fadd_rn(__fadd_rn(ah1, fr1), bias);

    float* outp = g_c1 + ((size_t)tb*20 + cch)*576;
    *(float2*)&outp[(y0  )*24 + x0] = make_float2(s00, s01);
    *(float2*)&outp[(y0+1)*24 + x0] = make_float2(s10, s11);
}

// ---------------- K2: ALL 64 timesteps, persistent (samples independent) ----
// grid 128, block 1024 = two independent 512-thread halves (one sample each),
// synced by named barriers. Conv2 uses BYTE tables (8 terms/load); FC nibble.
__global__ __launch_bounds__(1024) void k_steps(
    const float* __restrict__ b2, const float* __restrict__ b_fc,
    float* __restrict__ volt)
{
    __shared__ float s_in[2][2880];
    __shared__ int   s_off[512];
    __shared__ float s_sp1[2][800];
    __shared__ float s_z2[2][512];

    int half = threadIdx.x >> 9;
    int tid  = threadIdx.x & 511;
    int b    = blockIdx.x*2 + half;
    int lane = tid & 31;
    int warp = tid >> 5;              // 0..15 within half
    int barid = 1 + half;

    if (threadIdx.x < 512) {
        int tt = (threadIdx.x < 500) ? (int)threadIdx.x : 0;
        int ci = tt / 25, k = tt % 25;
        s_off[threadIdx.x] = ci*144 + (k/5)*12 + (k%5);
    }

    int yp = warp >> 2, xq = warp & 3;
    int co = lane, co2 = lane + 32;
    float bias0 = __ldg(&b2[co]);
    float bias1 = (co2 < 50) ? __ldg(&b2[co2]) : 0.f;
    float biasf = (tid < 500) ? __ldg(&b_fc[tid]) : 0.f;
    float* v0p = g_v0 + b*11520;
    float* i0p = g_i0 + b*11520;

    __syncthreads();                  // s_off visible to both halves

    for (int t = 0; t < TSTEPS; t++) {
        // ---- Phase A: LIF0 + pool ----
        {
            const float* c1 = g_c1 + ((size_t)t*BATCH + b)*11520;
            for (int q = tid; q < 2880; q += 512) {
                int c = q / 144, rr = q % 144;
                int r = rr / 12, xx = rr % 12;
                int base = (c*24 + 2*r)*24 + 2*xx;
                float zmax = 0.f;
#pragma unroll
                for (int dy = 0; dy < 2; dy++) {
                    int idx = base + dy*24;
                    float2 inp = *(const float2*)&c1[idx];
                    float2 v  = *(float2*)&v0p[idx];
                    float2 ii = *(float2*)&i0p[idx];
                    float z0, z1;
                    lif_update(v.x, ii.x, inp.x, z0);
                    lif_update(v.y, ii.y, inp.y, z1);
                    *(float2*)&v0p[idx] = v;
                    *(float2*)&i0p[idx] = ii;
                    zmax = fmaxf(zmax, fmaxf(z0, z1));
                }
                s_in[half][q] = zmax;
            }
        }
        asm volatile("bar.sync %0, 512;" :: "r"(barid) : "memory");

        // ---- Phase B: conv2 + LIF1 + pool (byte tables, 8 terms/load) ----
        {
            float z0max = 0.f, z1max = 0.f;
#pragma unroll
            for (int sp = 0; sp < 4; sp++) {
                int dy = sp >> 1, dx = sp & 1;
                int y = 2*yp + dy, x = 2*xq + dx;
                int base = y*12 + x;

                long long acc0 = 0, acc1 = 0;
#pragma unroll 1
                for (int ch = 0; ch < 16; ch++) {
                    float a = s_in[half][s_off[ch*32 + lane] + base];
                    unsigned msk = __ballot_sync(0xffffffffu, a != 0.f);
#pragma unroll
                    for (int j = 0; j < 4; j++) {
                        unsigned idx = (msk >> (8*j)) & 255u;
                        if (idx) {
                            const longlong2 wv = *(const longlong2*)
                                &g_tb2b[((ch*4 + j)*256 + idx)*64 + lane*2];
                            acc0 += wv.x;
                            acc1 += wv.y;
                        }
                    }
                }
                float inp0 = __fmul_rn(10.0f, __fadd_rn(fx2f(acc0), bias0));
                float inp1 = __fmul_rn(10.0f, __fadd_rn(fx2f(acc1), bias1));

                int sidx = (b*64 + y*8 + x)*64 + lane;
                float v0 = g_v1[sidx],      i0 = g_i1[sidx];
                float v1 = g_v1[sidx + 32], i1 = g_i1[sidx + 32];
                float z0, z1;
                lif_update(v0, i0, inp0, z0);
                lif_update(v1, i1, inp1, z1);
                g_v1[sidx] = v0;      g_i1[sidx] = i0;
                g_v1[sidx + 32] = v1; g_i1[sidx + 32] = i1;
                z0max = fmaxf(z0max, z0);
                z1max = fmaxf(z1max, z1);
            }
            int pos = yp*4 + xq;
            s_sp1[half][co*16 + pos] = z0max;
            if (co2 < 50) s_sp1[half][co2*16 + pos] = z1max;
        }
        asm volatile("bar.sync %0, 512;" :: "r"(barid) : "memory");

        // ---- Phase C: FC + LIF2 (nibble tables) ----
        {
            int m = tid;
            long long acc = 0;
#pragma unroll 1
            for (int ch = 0; ch < 25; ch++) {
                float a = s_sp1[half][ch*32 + lane];
                unsigned msk = __ballot_sync(0xffffffffu, a != 0.f);
#pragma unroll
                for (int j = 0; j < 8; j++) {
                    unsigned idx = (msk >> (4*j)) & 15u;
                    if (idx)
                        acc += __ldg(&g_tbf[((ch*8 + j)*16 + idx)*512 + m]);
                }
            }
            float inp = __fadd_rn(fx2f(acc), biasf);

            int sidx = b*512 + m;
            float v = g_v2[sidx], ii = g_i2[sidx];
            float z;
            lif_update(v, ii, inp, z);
            g_v2[sidx] = v;
            g_i2[sidx] = ii;
            s_z2[half][m] = (m < 500) ? z : 0.f;
        }
        asm volatile("bar.sync %0, 512;" :: "r"(barid) : "memory");

        // ---- Phase D: readout + LI ----
        if (warp < 10) {
            long long ao = 0;
            const long long* wr = g_woutll + warp*500;
#pragma unroll 1
            for (int j = lane; j < 500; j += 32)
                if (s_z2[half][j] != 0.f) ao += __ldg(wr + j);
#pragma unroll
            for (int off = 16; off; off >>= 1)
                ao += __shfl_xor_sync(0xffffffffu, ao, off);
            if (lane == 0) {
                float sum = fx2f(ao);
                int idx = b*10 + warp;
                float vo = g_vo[idx], io = g_io[idx];
                float vn = __fadd_rn(vo, __fmul_rn(LIF_BETA, __fsub_rn(io, vo)));
                g_vo[idx] = vn;
                g_io[idx] = __fadd_rn(__fmul_rn(LIF_IDEC, io), sum);
                volt[((size_t)t * BATCH + b)*10 + warp] = vn;
            }
        }
        asm volatile("bar.sync %0, 512;" :: "r"(barid) : "memory");
    }
}

// ---------------- launch -----------------------------------------------------
extern "C" void kernel_launch(void* const* d_in, const int* in_sizes, int n_in,
                              void* d_out, int out_size)
{
    const float* x     = (const float*)d_in[0];
    const float* w1    = (const float*)d_in[1];
    const float* b1    = (const float*)d_in[2];
    const float* w2    = (const float*)d_in[3];
    const float* b2    = (const float*)d_in[4];
    const float* w_fc  = (const float*)d_in[5];
    const float* b_fc  = (const float*)d_in[6];
    const float* w_out = (const float*)d_in[7];
    float* volt = (float*)d_out;

    zero_states<<<(BATCH*20*576 + 255)/256, 256>>>();
    prep_weights<<<(800*512 + 255)/256, 256>>>(w2, w_fc, w_out);
    prep_tables<<<(200*16*512 + 255)/256, 256>>>();

    dim3 gc1(BATCH*TSTEPS, 20);
    k_conv1_all<<<gc1, 160>>>(x, w1, b1);

    k_steps<<<BATCH/2, 1024>>>(b2, b_fc, volt);
}